// round 14
// baseline (speedup 1.0000x reference)
#include <cuda_runtime.h>
#include <cuda_bf16.h>
#include <math.h>
#include <stddef.h>
#include <stdint.h>

// ---------------------------------------------------------------------------
// Problem constants
// ---------------------------------------------------------------------------
#define NN   8192      // nodes per graph
#define HDIM 256       // hidden dim
#define DIN0 128       // input feature dim

// ---------------------------------------------------------------------------
// Static device scratch (no allocations allowed)
// ---------------------------------------------------------------------------
__device__ float g_sim[(size_t)NN * NN];            // 256 MB fp32 similarity
__device__ __nv_bfloat16 g_Pr[(size_t)NN * NN];     // exp(sim - rmax) bf16
__device__ __nv_bfloat16 g_Pc[(size_t)NN * NN];     // exp(sim^T - cmax) bf16
__device__ __nv_bfloat16 g_fh1[NN * HDIM], g_fl1[NN * HDIM];
__device__ __nv_bfloat16 g_fh2[NN * HDIM], g_fl2[NN * HDIM];
__device__ __nv_bfloat16 g_f1T[HDIM * NN], g_f2T[HDIM * NN];
__device__ float g_h1[NN * HDIM], g_h2[NN * HDIM];
__device__ float g_c1[NN * HDIM], g_c2[NN * HDIM];
__device__ float g_att1[NN * HDIM], g_att2[NN * HDIM];
__device__ float g_fa1[NN * HDIM], g_fa2[NN * HDIM];
__device__ float g_fb1[NN * HDIM], g_fb2[NN * HDIM];
__device__ __nv_bfloat16 g_cath1[NN * 768], g_catl1[NN * 768];
__device__ __nv_bfloat16 g_cath2[NN * 768], g_catl2[NN * 768];
__device__ float g_rmax[NN], g_rsum[NN], g_cmax[NN], g_csum[NN];
__device__ float g_band[8 * NN * 2];                // per-band col (max,sum) partials
__device__ float g_dinv1[NN], g_dinv2[NN];
__device__ float g_p[2 * HDIM];
__device__ float g_tmp[HDIM * 32];
// transposed + hi/lo split weights (bf16), done once per launch
__device__ __nv_bfloat16 g_gcnWT_h[3][HDIM * HDIM], g_gcnWT_l[3][HDIM * HDIM];
__device__ __nv_bfloat16 g_updWT_h[3][HDIM * 768], g_updWT_l[3][HDIM * 768];
__device__ __nv_bfloat16 g_gatedWT_h[HDIM * HDIM], g_gatedWT_l[HDIM * HDIM];

// ---------------------------------------------------------------------------
// mma.sync helpers (portable tensor-core path, valid on base sm_103 target)
// ---------------------------------------------------------------------------
__device__ __forceinline__ uint32_t smem_u32(const void* p) {
    uint32_t a;
    asm("{ .reg .u64 t; cvta.to.shared.u64 t, %1; cvt.u32.u64 %0, t; }"
        : "=r"(a) : "l"(p));
    return a;
}
__device__ __forceinline__ void ldmx4(uint32_t* r, uint32_t addr) {
    asm volatile("ldmatrix.sync.aligned.m8n8.x4.shared.b16 {%0,%1,%2,%3}, [%4];"
        : "=r"(r[0]), "=r"(r[1]), "=r"(r[2]), "=r"(r[3]) : "r"(addr));
}
__device__ __forceinline__ void mma16816(float* d, const uint32_t* a, const uint32_t* b) {
    asm volatile("mma.sync.aligned.m16n8k16.row.col.f32.bf16.bf16.f32 "
        "{%0,%1,%2,%3}, {%4,%5,%6,%7}, {%8,%9}, {%0,%1,%2,%3};"
        : "+f"(d[0]), "+f"(d[1]), "+f"(d[2]), "+f"(d[3])
        : "r"(a[0]), "r"(a[1]), "r"(a[2]), "r"(a[3]), "r"(b[0]), "r"(b[1]));
}
__device__ __forceinline__ void cp16(uint32_t dst, const void* src) {
    asm volatile("cp.async.cg.shared.global [%0], [%1], 16;" :: "r"(dst), "l"(src));
}

// ---------------------------------------------------------------------------
// Generic bf16 tensor-core GEMM (128x64 tile): C[M,N] = A @ B^T
//   SPLIT=1: hi/lo pairs; D = Ah*Bh + Ah*Bl + Al*Bh (~fp32)
//   SCALE=1: C row m multiplied by 1/vsum[m]
//   bias/act epilogue (act: 0 none, 1 tanh, 2 sigmoid)
// 8 warps (4x2), warp tile 32x32, K chunks of 64, 2-stage cp.async.
// ---------------------------------------------------------------------------
#define BKCH 64
#define A_TB 16384   // 128 rows * 128B
#define B_TB 8192    // 64 rows * 128B

template<int SPLIT, int SCALE>
__global__ void __launch_bounds__(256)
mma_gemm(const __nv_bfloat16* __restrict__ Ah, const __nv_bfloat16* __restrict__ Al,
         const __nv_bfloat16* __restrict__ Bh, const __nv_bfloat16* __restrict__ Bl,
         float* __restrict__ C, int N, int K, const float* __restrict__ vsum,
         const float* __restrict__ bias, int act)
{
    extern __shared__ char smem[];
    const uint32_t sb = smem_u32(smem);
    const int tid = threadIdx.x;
    const int wid = tid >> 5, lane = tid & 31;
    const int warp_m = wid & 3, warp_n = wid >> 2;      // 4 x 2 warp grid
    const int m0 = blockIdx.y * 128, n0 = blockIdx.x * 64;
    const uint32_t BUFB = SPLIT ? (2 * A_TB + 2 * B_TB) : (A_TB + B_TB);
    const uint32_t BOFF = SPLIT ? 2 * A_TB : A_TB;

    auto issue = [&](int ch, int buf) {
        const uint32_t base = sb + buf * BUFB;
#pragma unroll
        for (int g = 0; g < 4; g++) {          // A tile: 128 rows x 8 x 16B
            const int idx = tid * 4 + g;
            const int row = idx >> 3, c16 = idx & 7;
            uint32_t off = row * 128 + c16 * 16;
            uint32_t sw = off ^ ((off >> 3) & 0x70);
            const char* s = (const char*)(Ah + (size_t)(m0 + row) * K + ch * BKCH) + c16 * 16;
            cp16(base + sw, s);
            if (SPLIT) {
                const char* sl = (const char*)(Al + (size_t)(m0 + row) * K + ch * BKCH) + c16 * 16;
                cp16(base + A_TB + sw, sl);
            }
        }
#pragma unroll
        for (int g = 0; g < 2; g++) {          // B tile: 64 rows x 8 x 16B
            const int idx = tid * 2 + g;
            const int row = idx >> 3, c16 = idx & 7;
            uint32_t off = row * 128 + c16 * 16;
            uint32_t sw = off ^ ((off >> 3) & 0x70);
            const char* s = (const char*)(Bh + (size_t)(n0 + row) * K + ch * BKCH) + c16 * 16;
            cp16(base + BOFF + sw, s);
            if (SPLIT) {
                const char* sl = (const char*)(Bl + (size_t)(n0 + row) * K + ch * BKCH) + c16 * 16;
                cp16(base + BOFF + B_TB + sw, sl);
            }
        }
        asm volatile("cp.async.commit_group;" ::: "memory");
    };

    float acc[2][4][4];
#pragma unroll
    for (int i = 0; i < 2; i++)
#pragma unroll
        for (int j = 0; j < 4; j++)
#pragma unroll
            for (int q = 0; q < 4; q++) acc[i][j][q] = 0.f;

    const int nch = K / BKCH;
    issue(0, 0);
    for (int c = 0; c < nch; c++) {
        if (c + 1 < nch) {
            issue(c + 1, (c + 1) & 1);
            asm volatile("cp.async.wait_group 1;" ::: "memory");
        } else {
            asm volatile("cp.async.wait_group 0;" ::: "memory");
        }
        __syncthreads();
        const uint32_t base = sb + (c & 1) * BUFB;
        const uint32_t aB = base, alB = base + A_TB;
        const uint32_t bB = base + BOFF, blB = base + BOFF + B_TB;
#pragma unroll
        for (int kk = 0; kk < 4; kk++) {
            uint32_t ah[2][4], al[2][4];
#pragma unroll
            for (int mt = 0; mt < 2; mt++) {
                const int row = warp_m * 32 + mt * 16 + (lane & 7) + ((lane >> 3) & 1) * 8;
                uint32_t off = row * 128 + kk * 32 + (lane >> 4) * 16;
                uint32_t sw = off ^ ((off >> 3) & 0x70);
                ldmx4(ah[mt], aB + sw);
                if (SPLIT) ldmx4(al[mt], alB + sw);
            }
            uint32_t bh[4][2], bl[4][2];
#pragma unroll
            for (int np = 0; np < 2; np++) {
                const int row = warp_n * 32 + np * 16 + (lane & 7) + ((lane >> 3) & 1) * 8;
                uint32_t off = row * 128 + kk * 32 + (lane >> 4) * 16;
                uint32_t sw = off ^ ((off >> 3) & 0x70);
                uint32_t r[4];
                ldmx4(r, bB + sw);
                bh[np * 2][0] = r[0]; bh[np * 2][1] = r[2];
                bh[np * 2 + 1][0] = r[1]; bh[np * 2 + 1][1] = r[3];
                if (SPLIT) {
                    ldmx4(r, blB + sw);
                    bl[np * 2][0] = r[0]; bl[np * 2][1] = r[2];
                    bl[np * 2 + 1][0] = r[1]; bl[np * 2 + 1][1] = r[3];
                }
            }
#pragma unroll
            for (int mt = 0; mt < 2; mt++)
#pragma unroll
                for (int nt = 0; nt < 4; nt++) {
                    mma16816(acc[mt][nt], ah[mt], bh[nt]);
                    if (SPLIT) {
                        mma16816(acc[mt][nt], ah[mt], bl[nt]);
                        mma16816(acc[mt][nt], al[mt], bh[nt]);
                    }
                }
        }
        __syncthreads();
    }

    const int r = lane >> 2, cg = (lane & 3) * 2;
#pragma unroll
    for (int mt = 0; mt < 2; mt++) {
        const int mrow = m0 + warp_m * 32 + mt * 16 + r;
        const float s0 = SCALE ? (1.f / vsum[mrow]) : 1.f;
        const float s8 = SCALE ? (1.f / vsum[mrow + 8]) : 1.f;
#pragma unroll
        for (int nt = 0; nt < 4; nt++) {
            const int ncol = n0 + warp_n * 32 + nt * 8 + cg;
            float b0 = 0.f, b1 = 0.f;
            if (bias) { b0 = bias[ncol]; b1 = bias[ncol + 1]; }
            float4 v;
            v.x = acc[mt][nt][0] * s0 + b0;
            v.y = acc[mt][nt][1] * s0 + b1;
            v.z = acc[mt][nt][2] * s8 + b0;
            v.w = acc[mt][nt][3] * s8 + b1;
            if (act == 1) {
                v.x = tanhf(v.x); v.y = tanhf(v.y); v.z = tanhf(v.z); v.w = tanhf(v.w);
            } else if (act == 2) {
                v.x = 1.f / (1.f + __expf(-v.x)); v.y = 1.f / (1.f + __expf(-v.y));
                v.z = 1.f / (1.f + __expf(-v.z)); v.w = 1.f / (1.f + __expf(-v.w));
            }
            *(float2*)(C + (size_t)mrow * N + ncol) = make_float2(v.x, v.y);
            *(float2*)(C + (size_t)(mrow + 8) * N + ncol) = make_float2(v.z, v.w);
        }
    }
}

// ---------------------------------------------------------------------------
// Big-tile (128x128) split-bf16 GEMM, used ONLY for sim (grid 64x64).
// 8 warps (2x4), warp tile 64x32. Verified correct in Round 8.
// ---------------------------------------------------------------------------
#define B_TB2 16384  // 128 rows * 128B

__global__ void __launch_bounds__(256)
mma_gemm_big(const __nv_bfloat16* __restrict__ Ah, const __nv_bfloat16* __restrict__ Al,
             const __nv_bfloat16* __restrict__ Bh, const __nv_bfloat16* __restrict__ Bl,
             float* __restrict__ C, int N, int K)
{
    extern __shared__ char smem[];
    const uint32_t sb = smem_u32(smem);
    const int tid = threadIdx.x;
    const int wid = tid >> 5, lane = tid & 31;
    const int warp_m = wid & 1, warp_n = wid >> 1;      // 2 x 4 warp grid
    const int m0 = blockIdx.y * 128, n0 = blockIdx.x * 128;
    const uint32_t BUFB = 2 * A_TB + 2 * B_TB2;
    const uint32_t BOFF = 2 * A_TB;

    auto issue = [&](int ch, int buf) {
        const uint32_t base = sb + buf * BUFB;
#pragma unroll
        for (int g = 0; g < 4; g++) {          // A tile: 128 rows x 8 x 16B
            const int idx = tid * 4 + g;
            const int row = idx >> 3, c16 = idx & 7;
            uint32_t off = row * 128 + c16 * 16;
            uint32_t sw = off ^ ((off >> 3) & 0x70);
            const char* s = (const char*)(Ah + (size_t)(m0 + row) * K + ch * BKCH) + c16 * 16;
            cp16(base + sw, s);
            const char* sl = (const char*)(Al + (size_t)(m0 + row) * K + ch * BKCH) + c16 * 16;
            cp16(base + A_TB + sw, sl);
        }
#pragma unroll
        for (int g = 0; g < 4; g++) {          // B tile: 128 rows x 8 x 16B
            const int idx = tid * 4 + g;
            const int row = idx >> 3, c16 = idx & 7;
            uint32_t off = row * 128 + c16 * 16;
            uint32_t sw = off ^ ((off >> 3) & 0x70);
            const char* s = (const char*)(Bh + (size_t)(n0 + row) * K + ch * BKCH) + c16 * 16;
            cp16(base + BOFF + sw, s);
            const char* sl = (const char*)(Bl + (size_t)(n0 + row) * K + ch * BKCH) + c16 * 16;
            cp16(base + BOFF + B_TB2 + sw, sl);
        }
        asm volatile("cp.async.commit_group;" ::: "memory");
    };

    float acc[4][4][4];
#pragma unroll
    for (int i = 0; i < 4; i++)
#pragma unroll
        for (int j = 0; j < 4; j++)
#pragma unroll
            for (int q = 0; q < 4; q++) acc[i][j][q] = 0.f;

    const int nch = K / BKCH;
    issue(0, 0);
    for (int c = 0; c < nch; c++) {
        if (c + 1 < nch) {
            issue(c + 1, (c + 1) & 1);
            asm volatile("cp.async.wait_group 1;" ::: "memory");
        } else {
            asm volatile("cp.async.wait_group 0;" ::: "memory");
        }
        __syncthreads();
        const uint32_t base = sb + (c & 1) * BUFB;
        const uint32_t aB = base, alB = base + A_TB;
        const uint32_t bB = base + BOFF, blB = base + BOFF + B_TB2;
#pragma unroll
        for (int kk = 0; kk < 4; kk++) {
            uint32_t ah[4][4], al[4][4];
#pragma unroll
            for (int mt = 0; mt < 4; mt++) {
                const int row = warp_m * 64 + mt * 16 + (lane & 15);
                uint32_t off = row * 128 + kk * 32 + (lane >> 4) * 16;
                uint32_t sw = off ^ ((off >> 3) & 0x70);
                ldmx4(ah[mt], aB + sw);
                ldmx4(al[mt], alB + sw);
            }
            uint32_t bh[4][2], bl[4][2];
#pragma unroll
            for (int np = 0; np < 2; np++) {
                const int row = warp_n * 32 + np * 16 + (lane & 15);
                uint32_t off = row * 128 + kk * 32 + (lane >> 4) * 16;
                uint32_t sw = off ^ ((off >> 3) & 0x70);
                uint32_t r[4];
                ldmx4(r, bB + sw);
                bh[np * 2][0] = r[0]; bh[np * 2][1] = r[2];
                bh[np * 2 + 1][0] = r[1]; bh[np * 2 + 1][1] = r[3];
                ldmx4(r, blB + sw);
                bl[np * 2][0] = r[0]; bl[np * 2][1] = r[2];
                bl[np * 2 + 1][0] = r[1]; bl[np * 2 + 1][1] = r[3];
            }
#pragma unroll
            for (int mt = 0; mt < 4; mt++)
#pragma unroll
                for (int nt = 0; nt < 4; nt++) {
                    mma16816(acc[mt][nt], ah[mt], bh[nt]);
                    mma16816(acc[mt][nt], ah[mt], bl[nt]);
                    mma16816(acc[mt][nt], al[mt], bh[nt]);
                }
        }
        __syncthreads();
    }

    const int r = lane >> 2, cg = (lane & 3) * 2;
#pragma unroll
    for (int mt = 0; mt < 4; mt++) {
        const int mrow = m0 + warp_m * 64 + mt * 16 + r;
#pragma unroll
        for (int nt = 0; nt < 4; nt++) {
            const int ncol = n0 + warp_n * 32 + nt * 8 + cg;
            *(float2*)(C + (size_t)mrow * N + ncol) =
                make_float2(acc[mt][nt][0], acc[mt][nt][1]);
            *(float2*)(C + (size_t)(mrow + 8) * N + ncol) =
                make_float2(acc[mt][nt][2], acc[mt][nt][3]);
        }
    }
}

// ---------------------------------------------------------------------------
// Conversions
// ---------------------------------------------------------------------------
__global__ void split_bf16_kernel(const float* __restrict__ f,
                                  __nv_bfloat16* __restrict__ hi,
                                  __nv_bfloat16* __restrict__ lo, int n) {
    int i = blockIdx.x * 256 + threadIdx.x;
    if (i >= n) return;
    float x = f[i];
    __nv_bfloat16 h = __float2bfloat16(x);
    hi[i] = h;
    lo[i] = __float2bfloat16(x - __bfloat162float(h));
}

__global__ void transpose_bf16_kernel(const float* __restrict__ f,
                                      __nv_bfloat16* __restrict__ fT, int din) {
    __shared__ float t[32][33];
    const int bx = blockIdx.x * 32, by = blockIdx.y * 32;
    const int x = threadIdx.x, y = threadIdx.y;  // (32, 8)
#pragma unroll
    for (int i = 0; i < 4; i++)
        t[y + 8 * i][x] = f[(size_t)(by + y + 8 * i) * din + bx + x];
    __syncthreads();
#pragma unroll
    for (int i = 0; i < 4; i++)
        fT[(size_t)(bx + y + 8 * i) * NN + by + x] = __float2bfloat16(t[x][y + 8 * i]);
}

__global__ void wtsplit_kernel(const float* __restrict__ W,
                               __nv_bfloat16* __restrict__ hiT,
                               __nv_bfloat16* __restrict__ loT, int K, int N) {
    __shared__ float t[32][33];
    const int bx = blockIdx.x * 32, by = blockIdx.y * 32;   // bx: K, by: N
    const int x = threadIdx.x, y = threadIdx.y;
#pragma unroll
    for (int i = 0; i < 4; i++)
        t[y + 8 * i][x] = W[(size_t)(bx + y + 8 * i) * N + by + x];
    __syncthreads();
#pragma unroll
    for (int i = 0; i < 4; i++) {
        float v = t[x][y + 8 * i];
        __nv_bfloat16 h = __float2bfloat16(v);
        size_t o = (size_t)(by + y + 8 * i) * K + bx + x;
        hiT[o] = h;
        loT[o] = __float2bfloat16(v - __bfloat162float(h));
    }
}

__global__ void exp_convert_kernel(const float* __restrict__ sim,
                                   const float* __restrict__ rmax,
                                   const float* __restrict__ cmax,
                                   __nv_bfloat16* __restrict__ Pr,
                                   __nv_bfloat16* __restrict__ Pc) {
    __shared__ float t[32][33];
    const int bx = blockIdx.x * 32, by = blockIdx.y * 32;
    const int x = threadIdx.x, y = threadIdx.y;  // (32, 8)
    const float cm = cmax[bx + x];
#pragma unroll
    for (int i = 0; i < 4; i++) {
        const int r = by + y + 8 * i;
        float v = sim[(size_t)r * NN + bx + x];
        Pr[(size_t)r * NN + bx + x] = __float2bfloat16(__expf(v - rmax[r]));
        t[y + 8 * i][x] = __expf(v - cm);
    }
    __syncthreads();
#pragma unroll
    for (int i = 0; i < 4; i++)
        Pc[(size_t)(bx + y + 8 * i) * NN + by + x] = __float2bfloat16(t[x][y + 8 * i]);
}

// ---------------------------------------------------------------------------
// Degree / normalization, GCN scatter
// ---------------------------------------------------------------------------
__global__ void fill1_kernel(float* d, int n) {
    int i = blockIdx.x * 256 + threadIdx.x;
    if (i < n) d[i] = 1.0f;
}
__global__ void degcnt_kernel(const int* __restrict__ dst, int E, float* deg) {
    int e = blockIdx.x * 256 + threadIdx.x;
    if (e < E) atomicAdd(&deg[dst[e]], 1.0f);
}
__global__ void rsqrt_kernel(float* d, int n) {
    int i = blockIdx.x * 256 + threadIdx.x;
    if (i < n) d[i] = rsqrtf(d[i]);
}
__global__ void gcn_self_kernel(const float* __restrict__ h,
                                const float* __restrict__ dinv,
                                float* __restrict__ c) {
    int idx = blockIdx.x * 256 + threadIdx.x;
    int v = idx >> 8;
    float dv = dinv[v];
    c[idx] = dv * dv * h[idx];
}
__global__ void gcn_scatter_kernel(const int* __restrict__ src,
                                   const int* __restrict__ dst,
                                   const float* __restrict__ dinv,
                                   const float* __restrict__ h,
                                   float* __restrict__ c) {
    int e = blockIdx.x;
    int s = src[e], d = dst[e];
    float w = dinv[s] * dinv[d];
    atomicAdd(&c[(size_t)d * HDIM + threadIdx.x],
              w * h[(size_t)s * HDIM + threadIdx.x]);
}

// ---------------------------------------------------------------------------
// Online softmax statistics over fp32 sim
// ---------------------------------------------------------------------------
__device__ __forceinline__ void sm_combine(float& m, float& s, float m2, float s2) {
    float M = fmaxf(m, m2);
    s = s * __expf(m - M) + s2 * __expf(m2 - M);
    m = M;
}
__global__ void rowstats_kernel(const float* __restrict__ sim,
                                float* __restrict__ rmax, float* __restrict__ rsum) {
    const int row = blockIdx.x;
    const float* p = sim + (size_t)row * NN;
    float m = -1e30f, s = 0.f;
    for (int c = threadIdx.x; c < NN; c += 256) {
        float x = p[c];
        if (x > m) { s = s * __expf(m - x) + 1.f; m = x; }
        else       { s += __expf(x - m); }
    }
#pragma unroll
    for (int o = 16; o > 0; o >>= 1) {
        float m2 = __shfl_xor_sync(0xffffffffu, m, o);
        float s2 = __shfl_xor_sync(0xffffffffu, s, o);
        sm_combine(m, s, m2, s2);
    }
    __shared__ float sm[8], ss[8];
    int w = threadIdx.x >> 5, l = threadIdx.x & 31;
    if (l == 0) { sm[w] = m; ss[w] = s; }
    __syncthreads();
    if (threadIdx.x == 0) {
        m = sm[0]; s = ss[0];
        for (int i = 1; i < 8; i++) sm_combine(m, s, sm[i], ss[i]);
        rmax[row] = m; rsum[row] = s;
    }
}
__global__ void colstats_band_kernel(const float* __restrict__ sim,
                                     float* __restrict__ band) {
    const int col = blockIdx.x * 32 + threadIdx.x;
    const int y = threadIdx.y;
    const int r0 = blockIdx.y * (NN / 8);
    float m = -1e30f, s = 0.f;
    for (int r = r0 + y; r < r0 + NN / 8; r += 8) {
        float x = sim[(size_t)r * NN + col];
        if (x > m) { s = s * __expf(m - x) + 1.f; m = x; }
        else       { s += __expf(x - m); }
    }
    __shared__ float sm[8][32], ss[8][32];
    sm[y][threadIdx.x] = m; ss[y][threadIdx.x] = s;
    __syncthreads();
    if (y == 0) {
        for (int i = 1; i < 8; i++) sm_combine(m, s, sm[i][threadIdx.x], ss[i][threadIdx.x]);
        band[((size_t)blockIdx.y * NN + col) * 2]     = m;
        band[((size_t)blockIdx.y * NN + col) * 2 + 1] = s;
    }
}
__global__ void colmerge_kernel(const float* __restrict__ band,
                                float* __restrict__ cmax, float* __restrict__ csum) {
    int col = blockIdx.x * 256 + threadIdx.x;
    float m = band[(size_t)col * 2], s = band[(size_t)col * 2 + 1];
#pragma unroll
    for (int b = 1; b < 8; b++)
        sm_combine(m, s, band[((size_t)b * NN + col) * 2],
                         band[((size_t)b * NN + col) * 2 + 1]);
    cmax[col] = m; csum[col] = s;
}

// ---------------------------------------------------------------------------
// cat = [c | f | f - att] -> bf16 hi/lo (att rows have stride din)
// ---------------------------------------------------------------------------
__global__ void cat_split_kernel(const float* __restrict__ c, const float* __restrict__ f,
                                 const float* __restrict__ att,
                                 __nv_bfloat16* __restrict__ cath,
                                 __nv_bfloat16* __restrict__ catl, int din) {
    const int catw = HDIM + 2 * din;
    size_t idx = (size_t)blockIdx.x * 256 + threadIdx.x;
    if (idx >= (size_t)NN * catw) return;
    int r = (int)(idx / catw), col = (int)(idx % catw);
    float v;
    if (col < HDIM)            v = c[(size_t)r * HDIM + col];
    else if (col < HDIM + din) v = f[(size_t)r * din + (col - HDIM)];
    else {
        int cc = col - HDIM - din;
        v = f[(size_t)r * din + cc] - att[(size_t)r * din + cc];
    }
    __nv_bfloat16 h = __float2bfloat16(v);
    cath[idx] = h;
    catl[idx] = __float2bfloat16(v - __bfloat162float(h));
}

// ---------------------------------------------------------------------------
// Gated readout + NTN tail
// ---------------------------------------------------------------------------
__global__ void zero_kernel(float* p, int n) {
    int i = blockIdx.x * 256 + threadIdx.x;
    if (i < n) p[i] = 0.f;
}
__global__ void preduce_kernel(const float* __restrict__ z,
                               const float* __restrict__ f,
                               float* __restrict__ p) {
    const int c = threadIdx.x;
    const int r0 = blockIdx.x * 64;
    float acc = 0.f;
    for (int r = r0; r < r0 + 64; r++)
        acc += z[(size_t)r * HDIM + c] * f[(size_t)r * HDIM + c];
    atomicAdd(&p[c], acc);
}
__global__ void ntn1_kernel(const float* __restrict__ p1,
                            const float* __restrict__ W,
                            float* __restrict__ tmp) {
    int g = blockIdx.x * 256 + threadIdx.x;
    float acc = 0.f;
    for (int i = 0; i < HDIM; i++) acc += p1[i] * W[(size_t)i * 8192 + g];
    tmp[g] = acc;
}
__global__ void tail_kernel(const float* __restrict__ p1, const float* __restrict__ p2,
                            const float* __restrict__ tmp,
                            const float* __restrict__ Wb, const float* __restrict__ tnb,
                            const float* __restrict__ fc1W, const float* __restrict__ fc1b,
                            const float* __restrict__ scW, const float* __restrict__ scb,
                            const float* __restrict__ avgv,
                            float* __restrict__ out, int out_size) {
    __shared__ float ntn[32];
    __shared__ float sv[16];
    const int t = threadIdx.x;
    float acc = tnb[t];
    for (int j = 0; j < HDIM; j++) acc += tmp[j * 32 + t] * p2[j];
    for (int k = 0; k < HDIM; k++)
        acc += Wb[t * 512 + k] * p1[k] + Wb[t * 512 + HDIM + k] * p2[k];
    ntn[t] = fmaxf(acc, 0.f);
    __syncthreads();
    if (t < 16) {
        float a = fc1b[t];
        for (int q = 0; q < 32; q++) a += ntn[q] * fc1W[q * 16 + t];
        sv[t] = tanhf(a);
    }
    __syncthreads();
    if (t == 0) {
        float a = scb[0];
        for (int q = 0; q < 16; q++) a += sv[q] * scW[q];
        float sc = 1.f / (1.f + expf(-a));
        out[0] = sc;
        if (out_size > 1) out[1] = -logf(sc) * avgv[0];
    }
}

// ---------------------------------------------------------------------------
// Host launcher
// ---------------------------------------------------------------------------
extern "C" void kernel_launch(void* const* d_in, const int* in_sizes, int n_in,
                              void* d_out, int out_size)
{
    const float* f1in  = (const float*)d_in[0];
    const float* f2in  = (const float*)d_in[1];
    const int*   ei1   = (const int*)d_in[2];
    const int*   ei2   = (const int*)d_in[3];
    const float* avgv  = (const float*)d_in[4];
    const float* gcnW[3] = {(const float*)d_in[5], (const float*)d_in[8],  (const float*)d_in[11]};
    const float* updW[3] = {(const float*)d_in[6], (const float*)d_in[9],  (const float*)d_in[12]};
    const float* updb[3] = {(const float*)d_in[7], (const float*)d_in[10], (const float*)d_in[13]};
    const float* gatedW = (const float*)d_in[14];
    const float* gatedb = (const float*)d_in[15];
    const float* tnW  = (const float*)d_in[16];
    const float* tnWb = (const float*)d_in[17];
    const float* tnb  = (const float*)d_in[18];
    const float* fc1W = (const float*)d_in[19];
    const float* fc1b = (const float*)d_in[20];
    const float* scW  = (const float*)d_in[21];
    const float* scb  = (const float*)d_in[22];

    const int E = in_sizes[2] / 2;

    float *sim, *h1, *h2, *c1, *c2, *att1, *att2, *fa1, *fa2, *fb1, *fb2;
    float *rmax, *rsum, *cmax, *csum, *bandp, *dinv1, *dinv2, *pvec, *tmp;
    __nv_bfloat16 *Pr, *Pc, *fh1, *fl1, *fh2, *fl2, *f1T, *f2T;
    __nv_bfloat16 *cath1, *catl1, *cath2, *catl2;
    __nv_bfloat16 *gcnWTh, *gcnWTl, *updWTh, *updWTl, *gatedWTh, *gatedWTl;
    cudaGetSymbolAddress((void**)&sim,  g_sim);
    cudaGetSymbolAddress((void**)&Pr,   g_Pr);
    cudaGetSymbolAddress((void**)&Pc,   g_Pc);
    cudaGetSymbolAddress((void**)&fh1,  g_fh1);
    cudaGetSymbolAddress((void**)&fl1,  g_fl1);
    cudaGetSymbolAddress((void**)&fh2,  g_fh2);
    cudaGetSymbolAddress((void**)&fl2,  g_fl2);
    cudaGetSymbolAddress((void**)&f1T,  g_f1T);
    cudaGetSymbolAddress((void**)&f2T,  g_f2T);
    cudaGetSymbolAddress((void**)&h1,   g_h1);
    cudaGetSymbolAddress((void**)&h2,   g_h2);
    cudaGetSymbolAddress((void**)&c1,   g_c1);
    cudaGetSymbolAddress((void**)&c2,   g_c2);
    cudaGetSymbolAddress((void**)&att1, g_att1);
    cudaGetSymbolAddress((void**)&att2, g_att2);
    cudaGetSymbolAddress((void**)&fa1,  g_fa1);
    cudaGetSymbolAddress((void**)&fa2,  g_fa2);
    cudaGetSymbolAddress((void**)&fb1,  g_fb1);
    cudaGetSymbolAddress((void**)&fb2,  g_fb2);
    cudaGetSymbolAddress((void**)&cath1, g_cath1);
    cudaGetSymbolAddress((void**)&catl1, g_catl1);
    cudaGetSymbolAddress((void**)&cath2, g_cath2);
    cudaGetSymbolAddress((void**)&catl2, g_catl2);
    cudaGetSymbolAddress((void**)&rmax, g_rmax);
    cudaGetSymbolAddress((void**)&rsum, g_rsum);
    cudaGetSymbolAddress((void**)&cmax, g_cmax);
    cudaGetSymbolAddress((void**)&csum, g_csum);
    cudaGetSymbolAddress((void**)&bandp, g_band);
    cudaGetSymbolAddress((void**)&dinv1, g_dinv1);
    cudaGetSymbolAddress((void**)&dinv2, g_dinv2);
    cudaGetSymbolAddress((void**)&pvec, g_p);
    cudaGetSymbolAddress((void**)&tmp,  g_tmp);
    cudaGetSymbolAddress((void**)&gcnWTh, g_gcnWT_h);
    cudaGetSymbolAddress((void**)&gcnWTl, g_gcnWT_l);
    cudaGetSymbolAddress((void**)&updWTh, g_updWT_h);
    cudaGetSymbolAddress((void**)&updWTl, g_updWT_l);
    cudaGetSymbolAddress((void**)&gatedWTh, g_gatedWT_h);
    cudaGetSymbolAddress((void**)&gatedWTl, g_gatedWT_l);

    const int SMEM_SPLIT = 2 * (2 * A_TB + 2 * B_TB);    // 98304
    const int SMEM_PLAIN = 2 * (A_TB + B_TB);            // 49152
    const int SMEM_BIG   = 2 * (2 * A_TB + 2 * B_TB2);   // 131072
    cudaFuncSetAttribute(mma_gemm<1, 0>, cudaFuncAttributeMaxDynamicSharedMemorySize, SMEM_SPLIT);
    cudaFuncSetAttribute(mma_gemm<0, 1>, cudaFuncAttributeMaxDynamicSharedMemorySize, SMEM_PLAIN);
    cudaFuncSetAttribute(mma_gemm_big, cudaFuncAttributeMaxDynamicSharedMemorySize, SMEM_BIG);

    // --- one-time weight transpose + hi/lo split ---
    const dim3 wtb(32, 8);
    for (int L = 0; L < 3; L++) {
        const int dk = (L == 0) ? DIN0 : HDIM;
        const int cw = HDIM + 2 * dk;
        wtsplit_kernel<<<dim3(dk / 32, HDIM / 32), wtb>>>(
            gcnW[L], gcnWTh + L * HDIM * HDIM, gcnWTl + L * HDIM * HDIM, dk, HDIM);
        wtsplit_kernel<<<dim3(cw / 32, HDIM / 32), wtb>>>(
            updW[L], updWTh + L * HDIM * 768, updWTl + L * HDIM * 768, cw, HDIM);
    }
    wtsplit_kernel<<<dim3(HDIM / 32, HDIM / 32), wtb>>>(gatedW, gatedWTh, gatedWTl, HDIM, HDIM);

    // --- degree normalization ---
    fill1_kernel<<<(NN + 255) / 256, 256>>>(dinv1, NN);
    fill1_kernel<<<(NN + 255) / 256, 256>>>(dinv2, NN);
    degcnt_kernel<<<(E + 255) / 256, 256>>>(ei1 + E, E, dinv1);
    degcnt_kernel<<<(E + 255) / 256, 256>>>(ei2 + E, E, dinv2);
    rsqrt_kernel<<<(NN + 255) / 256, 256>>>(dinv1, NN);
    rsqrt_kernel<<<(NN + 255) / 256, 256>>>(dinv2, NN);

    const float* f1p = f1in;
    const float* f2p = f2in;
    int din = DIN0;

    for (int L = 0; L < 3; L++) {
        float* o1 = (L == 1) ? fa1 : fb1;
        float* o2 = (L == 1) ? fa2 : fb2;
        const __nv_bfloat16* gWh = gcnWTh + L * HDIM * HDIM;
        const __nv_bfloat16* gWl = gcnWTl + L * HDIM * HDIM;
        const __nv_bfloat16* uWh = updWTh + L * HDIM * 768;
        const __nv_bfloat16* uWl = updWTl + L * HDIM * 768;

        // bf16 forms of features
        split_bf16_kernel<<<NN * din / 256, 256>>>(f1p, fh1, fl1, NN * din);
        split_bf16_kernel<<<NN * din / 256, 256>>>(f2p, fh2, fl2, NN * din);
        transpose_bf16_kernel<<<dim3(din / 32, NN / 32), dim3(32, 8)>>>(f1p, f1T, din);
        transpose_bf16_kernel<<<dim3(din / 32, NN / 32), dim3(32, 8)>>>(f2p, f2T, din);

        // GCN: h = f @ Wg (split bf16 tensor)
        mma_gemm<1, 0><<<dim3(HDIM / 64, NN / 128), 256, SMEM_SPLIT>>>(
            fh1, fl1, gWh, gWl, h1, HDIM, din, nullptr, nullptr, 0);
        mma_gemm<1, 0><<<dim3(HDIM / 64, NN / 128), 256, SMEM_SPLIT>>>(
            fh2, fl2, gWh, gWl, h2, HDIM, din, nullptr, nullptr, 0);
        gcn_self_kernel<<<NN * HDIM / 256, 256>>>(h1, dinv1, c1);
        gcn_self_kernel<<<NN * HDIM / 256, 256>>>(h2, dinv2, c2);
        gcn_scatter_kernel<<<E, 256>>>(ei1, ei1 + E, dinv1, h1, c1);
        gcn_scatter_kernel<<<E, 256>>>(ei2, ei2 + E, dinv2, h2, c2);

        // sim = f1 @ f2^T (split bf16, 128x128 tile, grid 64x64)
        mma_gemm_big<<<dim3(NN / 128, NN / 128), 256, SMEM_BIG>>>(
            fh1, fl1, fh2, fl2, sim, NN, din);

        // softmax statistics (fp32): row stats + banded col stats
        rowstats_kernel<<<NN, 256>>>(sim, rmax, rsum);
        colstats_band_kernel<<<dim3(NN / 32, 8), dim3(32, 8)>>>(sim, bandp);
        colmerge_kernel<<<NN / 256, 256>>>(bandp, cmax, csum);

        // P matrices (bf16)
        exp_convert_kernel<<<dim3(NN / 32, NN / 32), dim3(32, 8)>>>(sim, rmax, cmax, Pr, Pc);

        // att1 = softmax_row(sim) @ f2 ; att2 = softmax_col(sim)^T @ f1
        mma_gemm<0, 1><<<dim3(din / 64, NN / 128), 256, SMEM_PLAIN>>>(
            Pr, nullptr, f2T, nullptr, att1, din, NN, rsum, nullptr, 0);
        mma_gemm<0, 1><<<dim3(din / 64, NN / 128), 256, SMEM_PLAIN>>>(
            Pc, nullptr, f1T, nullptr, att2, din, NN, csum, nullptr, 0);

        // cat (bf16 hi/lo) + update GEMM (+tanh except last layer)
        const int catw = HDIM + 2 * din;
        const int nel = NN * catw;
        cat_split_kernel<<<(nel + 255) / 256, 256>>>(c1, f1p, att1, cath1, catl1, din);
        cat_split_kernel<<<(nel + 255) / 256, 256>>>(c2, f2p, att2, cath2, catl2, din);
        const int act = (L == 2) ? 0 : 1;
        mma_gemm<1, 0><<<dim3(HDIM / 64, NN / 128), 256, SMEM_SPLIT>>>(
            cath1, catl1, uWh, uWl, o1, HDIM, catw, nullptr, updb[L], act);
        mma_gemm<1, 0><<<dim3(HDIM / 64, NN / 128), 256, SMEM_SPLIT>>>(
            cath2, catl2, uWh, uWl, o2, HDIM, catw, nullptr, updb[L], act);

        f1p = o1; f2p = o2; din = HDIM;
    }

    // --- gated readout (split bf16 tensor + sigmoid epilogue) ---
    split_bf16_kernel<<<NN * HDIM / 256, 256>>>(f1p, fh1, fl1, NN * HDIM);
    split_bf16_kernel<<<NN * HDIM / 256, 256>>>(f2p, fh2, fl2, NN * HDIM);
    mma_gemm<1, 0><<<dim3(HDIM / 64, NN / 128), 256, SMEM_SPLIT>>>(
        fh1, fl1, gatedWTh, gatedWTl, h1, HDIM, HDIM, nullptr, gatedb, 2);
    mma_gemm<1, 0><<<dim3(HDIM / 64, NN / 128), 256, SMEM_SPLIT>>>(
        fh2, fl2, gatedWTh, gatedWTl, h2, HDIM, HDIM, nullptr, gatedb, 2);
    zero_kernel<<<2, 256>>>(pvec, 2 * HDIM);
    preduce_kernel<<<NN / 64, 256>>>(h1, f1p, pvec);
    preduce_kernel<<<NN / 64, 256>>>(h2, f2p, pvec + HDIM);

    // --- NTN + head ---
    ntn1_kernel<<<32, 256>>>(pvec, tnW, tmp);
    tail_kernel<<<1, 32>>>(pvec, pvec + HDIM, tmp, tnWb, tnb,
                           fc1W, fc1b, scW, scb, avgv, (float*)d_out, out_size);
}

// round 16
// speedup vs baseline: 1.0440x; 1.0440x over previous
#include <cuda_runtime.h>
#include <cuda_bf16.h>
#include <math.h>
#include <stddef.h>
#include <stdint.h>

// ---------------------------------------------------------------------------
// Problem constants
// ---------------------------------------------------------------------------
#define NN   8192      // nodes per graph
#define HDIM 256       // hidden dim
#define DIN0 128       // input feature dim

// ---------------------------------------------------------------------------
// Static device scratch (no allocations allowed)
// ---------------------------------------------------------------------------
__device__ float g_sim[(size_t)NN * NN];            // 256 MB fp32 similarity
__device__ __nv_bfloat16 g_Pr[(size_t)NN * NN];     // exp(sim - rmax) bf16
__device__ __nv_bfloat16 g_Pc[(size_t)NN * NN];     // exp(sim^T - cmax) bf16
__device__ __nv_bfloat16 g_fh1[NN * HDIM], g_fl1[NN * HDIM];
__device__ __nv_bfloat16 g_fh2[NN * HDIM], g_fl2[NN * HDIM];
__device__ __nv_bfloat16 g_f1T[HDIM * NN], g_f2T[HDIM * NN];
__device__ float g_h1[NN * HDIM], g_h2[NN * HDIM];
__device__ float g_c1[NN * HDIM], g_c2[NN * HDIM];
__device__ float g_att1[NN * HDIM], g_att2[NN * HDIM];
__device__ float g_fa1[NN * HDIM], g_fa2[NN * HDIM];
__device__ float g_fb1[NN * HDIM], g_fb2[NN * HDIM];
__device__ __nv_bfloat16 g_cath1[NN * 768], g_catl1[NN * 768];
__device__ __nv_bfloat16 g_cath2[NN * 768], g_catl2[NN * 768];
__device__ float g_rmax[NN], g_rsum[NN], g_cmax[NN], g_csum[NN];
__device__ float g_band[8 * NN * 2];                // per-band col (max,sum) partials
__device__ float g_dinv1[NN], g_dinv2[NN];
__device__ float g_p[2 * HDIM];
__device__ float g_tmp[HDIM * 32];
// transposed + hi/lo split weights (bf16), done once per launch
__device__ __nv_bfloat16 g_gcnWT_h[3][HDIM * HDIM], g_gcnWT_l[3][HDIM * HDIM];
__device__ __nv_bfloat16 g_updWT_h[3][HDIM * 768], g_updWT_l[3][HDIM * 768];
__device__ __nv_bfloat16 g_gatedWT_h[HDIM * HDIM], g_gatedWT_l[HDIM * HDIM];

// ---------------------------------------------------------------------------
// mma.sync helpers (portable tensor-core path, valid on base sm_103 target)
// ---------------------------------------------------------------------------
__device__ __forceinline__ uint32_t smem_u32(const void* p) {
    uint32_t a;
    asm("{ .reg .u64 t; cvta.to.shared.u64 t, %1; cvt.u32.u64 %0, t; }"
        : "=r"(a) : "l"(p));
    return a;
}
__device__ __forceinline__ void ldmx4(uint32_t* r, uint32_t addr) {
    asm volatile("ldmatrix.sync.aligned.m8n8.x4.shared.b16 {%0,%1,%2,%3}, [%4];"
        : "=r"(r[0]), "=r"(r[1]), "=r"(r[2]), "=r"(r[3]) : "r"(addr));
}
__device__ __forceinline__ void mma16816(float* d, const uint32_t* a, const uint32_t* b) {
    asm volatile("mma.sync.aligned.m16n8k16.row.col.f32.bf16.bf16.f32 "
        "{%0,%1,%2,%3}, {%4,%5,%6,%7}, {%8,%9}, {%0,%1,%2,%3};"
        : "+f"(d[0]), "+f"(d[1]), "+f"(d[2]), "+f"(d[3])
        : "r"(a[0]), "r"(a[1]), "r"(a[2]), "r"(a[3]), "r"(b[0]), "r"(b[1]));
}
__device__ __forceinline__ void cp16(uint32_t dst, const void* src) {
    asm volatile("cp.async.cg.shared.global [%0], [%1], 16;" :: "r"(dst), "l"(src));
}

// ---------------------------------------------------------------------------
// bf16 tensor-core GEMM (128x64 tile): C[M,N] = A @ B^T (both K-major bf16)
//   SPLIT=1 : hi/lo pairs; D = Ah*Bh + Ah*Bl + Al*Bh (~fp32)
//   SCALE=1 : result row m multiplied by 1/vsum[m]
//   ATOMIC=1: accumulate into C via atomicAdd (split-K; C pre-zeroed;
//             blockIdx.z selects the K slice; bias must be null)
// 8 warps (4x2), warp tile 32x32, K chunks of 64, 2-stage cp.async.
// Requires M%128==0, N%64==0, K%(64*gridDim.z)==0.
// ---------------------------------------------------------------------------
#define BKCH 64
#define A_TB 16384   // 128 rows * 128B
#define B_TB 8192    // 64 rows * 128B

template<int SPLIT, int SCALE, int ATOMIC>
__global__ void __launch_bounds__(256)
mma_gemm(const __nv_bfloat16* __restrict__ Ah, const __nv_bfloat16* __restrict__ Al,
         const __nv_bfloat16* __restrict__ Bh, const __nv_bfloat16* __restrict__ Bl,
         float* __restrict__ C, int N, int K, const float* __restrict__ vsum,
         const float* __restrict__ bias, int act)
{
    extern __shared__ char smem[];
    const uint32_t sb = smem_u32(smem);
    const int tid = threadIdx.x;
    const int wid = tid >> 5, lane = tid & 31;
    const int warp_m = wid & 3, warp_n = wid >> 2;      // 4 x 2 warp grid
    const int m0 = blockIdx.y * 128, n0 = blockIdx.x * 64;
    const uint32_t BUFB = SPLIT ? (2 * A_TB + 2 * B_TB) : (A_TB + B_TB);
    const uint32_t BOFF = SPLIT ? 2 * A_TB : A_TB;

    auto issue = [&](int ch, int buf) {
        const uint32_t base = sb + buf * BUFB;
#pragma unroll
        for (int g = 0; g < 4; g++) {          // A tile: 128 rows x 8 x 16B
            const int idx = tid * 4 + g;
            const int row = idx >> 3, c16 = idx & 7;
            uint32_t off = row * 128 + c16 * 16;
            uint32_t sw = off ^ ((off >> 3) & 0x70);
            const char* s = (const char*)(Ah + (size_t)(m0 + row) * K + ch * BKCH) + c16 * 16;
            cp16(base + sw, s);
            if (SPLIT) {
                const char* sl = (const char*)(Al + (size_t)(m0 + row) * K + ch * BKCH) + c16 * 16;
                cp16(base + A_TB + sw, sl);
            }
        }
#pragma unroll
        for (int g = 0; g < 2; g++) {          // B tile: 64 rows x 8 x 16B
            const int idx = tid * 2 + g;
            const int row = idx >> 3, c16 = idx & 7;
            uint32_t off = row * 128 + c16 * 16;
            uint32_t sw = off ^ ((off >> 3) & 0x70);
            const char* s = (const char*)(Bh + (size_t)(n0 + row) * K + ch * BKCH) + c16 * 16;
            cp16(base + BOFF + sw, s);
            if (SPLIT) {
                const char* sl = (const char*)(Bl + (size_t)(n0 + row) * K + ch * BKCH) + c16 * 16;
                cp16(base + BOFF + B_TB + sw, sl);
            }
        }
        asm volatile("cp.async.commit_group;" ::: "memory");
    };

    float acc[2][4][4];
#pragma unroll
    for (int i = 0; i < 2; i++)
#pragma unroll
        for (int j = 0; j < 4; j++)
#pragma unroll
            for (int q = 0; q < 4; q++) acc[i][j][q] = 0.f;

    // K slice for this block (split-K via blockIdx.z; z==1 => full K)
    const int nch = (K / BKCH) / gridDim.z;
    const int ch0 = blockIdx.z * nch;

    issue(ch0, 0);
    for (int c = 0; c < nch; c++) {
        if (c + 1 < nch) {
            issue(ch0 + c + 1, (c + 1) & 1);
            asm volatile("cp.async.wait_group 1;" ::: "memory");
        } else {
            asm volatile("cp.async.wait_group 0;" ::: "memory");
        }
        __syncthreads();
        const uint32_t base = sb + (c & 1) * BUFB;
        const uint32_t aB = base, alB = base + A_TB;
        const uint32_t bB = base + BOFF, blB = base + BOFF + B_TB;
#pragma unroll
        for (int kk = 0; kk < 4; kk++) {
            uint32_t ah[2][4], al[2][4];
#pragma unroll
            for (int mt = 0; mt < 2; mt++) {
                const int row = warp_m * 32 + mt * 16 + (lane & 7) + ((lane >> 3) & 1) * 8;
                uint32_t off = row * 128 + kk * 32 + (lane >> 4) * 16;
                uint32_t sw = off ^ ((off >> 3) & 0x70);
                ldmx4(ah[mt], aB + sw);
                if (SPLIT) ldmx4(al[mt], alB + sw);
            }
            uint32_t bh[4][2], bl[4][2];
#pragma unroll
            for (int np = 0; np < 2; np++) {
                const int row = warp_n * 32 + np * 16 + (lane & 7) + ((lane >> 3) & 1) * 8;
                uint32_t off = row * 128 + kk * 32 + (lane >> 4) * 16;
                uint32_t sw = off ^ ((off >> 3) & 0x70);
                uint32_t r[4];
                ldmx4(r, bB + sw);
                bh[np * 2][0] = r[0]; bh[np * 2][1] = r[2];
                bh[np * 2 + 1][0] = r[1]; bh[np * 2 + 1][1] = r[3];
                if (SPLIT) {
                    ldmx4(r, blB + sw);
                    bl[np * 2][0] = r[0]; bl[np * 2][1] = r[2];
                    bl[np * 2 + 1][0] = r[1]; bl[np * 2 + 1][1] = r[3];
                }
            }
#pragma unroll
            for (int mt = 0; mt < 2; mt++)
#pragma unroll
                for (int nt = 0; nt < 4; nt++) {
                    mma16816(acc[mt][nt], ah[mt], bh[nt]);
                    if (SPLIT) {
                        mma16816(acc[mt][nt], ah[mt], bl[nt]);
                        mma16816(acc[mt][nt], al[mt], bh[nt]);
                    }
                }
        }
        __syncthreads();
    }

    // epilogue: thread holds (r, cg) within each 16x8 mma tile
    const int r = lane >> 2, cg = (lane & 3) * 2;
#pragma unroll
    for (int mt = 0; mt < 2; mt++) {
        const int mrow = m0 + warp_m * 32 + mt * 16 + r;
        const float s0 = SCALE ? (1.f / vsum[mrow]) : 1.f;
        const float s8 = SCALE ? (1.f / vsum[mrow + 8]) : 1.f;
#pragma unroll
        for (int nt = 0; nt < 4; nt++) {
            const int ncol = n0 + warp_n * 32 + nt * 8 + cg;
            if (ATOMIC) {
                atomicAdd(C + (size_t)mrow * N + ncol,           acc[mt][nt][0] * s0);
                atomicAdd(C + (size_t)mrow * N + ncol + 1,       acc[mt][nt][1] * s0);
                atomicAdd(C + (size_t)(mrow + 8) * N + ncol,     acc[mt][nt][2] * s8);
                atomicAdd(C + (size_t)(mrow + 8) * N + ncol + 1, acc[mt][nt][3] * s8);
            } else {
                float b0 = 0.f, b1 = 0.f;
                if (bias) { b0 = bias[ncol]; b1 = bias[ncol + 1]; }
                float4 v;
                v.x = acc[mt][nt][0] * s0 + b0;
                v.y = acc[mt][nt][1] * s0 + b1;
                v.z = acc[mt][nt][2] * s8 + b0;
                v.w = acc[mt][nt][3] * s8 + b1;
                if (act == 1) {
                    v.x = tanhf(v.x); v.y = tanhf(v.y); v.z = tanhf(v.z); v.w = tanhf(v.w);
                } else if (act == 2) {
                    v.x = 1.f / (1.f + __expf(-v.x)); v.y = 1.f / (1.f + __expf(-v.y));
                    v.z = 1.f / (1.f + __expf(-v.z)); v.w = 1.f / (1.f + __expf(-v.w));
                }
                *(float2*)(C + (size_t)mrow * N + ncol) = make_float2(v.x, v.y);
                *(float2*)(C + (size_t)(mrow + 8) * N + ncol) = make_float2(v.z, v.w);
            }
        }
    }
}

// ---------------------------------------------------------------------------
// Conversions
// ---------------------------------------------------------------------------
__global__ void split_bf16_kernel(const float* __restrict__ f,
                                  __nv_bfloat16* __restrict__ hi,
                                  __nv_bfloat16* __restrict__ lo, int n) {
    int i = blockIdx.x * 256 + threadIdx.x;
    if (i >= n) return;
    float x = f[i];
    __nv_bfloat16 h = __float2bfloat16(x);
    hi[i] = h;
    lo[i] = __float2bfloat16(x - __bfloat162float(h));
}

__global__ void transpose_bf16_kernel(const float* __restrict__ f,
                                      __nv_bfloat16* __restrict__ fT, int din) {
    __shared__ float t[32][33];
    const int bx = blockIdx.x * 32, by = blockIdx.y * 32;
    const int x = threadIdx.x, y = threadIdx.y;  // (32, 8)
#pragma unroll
    for (int i = 0; i < 4; i++)
        t[y + 8 * i][x] = f[(size_t)(by + y + 8 * i) * din + bx + x];
    __syncthreads();
#pragma unroll
    for (int i = 0; i < 4; i++)
        fT[(size_t)(bx + y + 8 * i) * NN + by + x] = __float2bfloat16(t[x][y + 8 * i]);
}

__global__ void wtsplit_kernel(const float* __restrict__ W,
                               __nv_bfloat16* __restrict__ hiT,
                               __nv_bfloat16* __restrict__ loT, int K, int N) {
    __shared__ float t[32][33];
    const int bx = blockIdx.x * 32, by = blockIdx.y * 32;   // bx: K, by: N
    const int x = threadIdx.x, y = threadIdx.y;
#pragma unroll
    for (int i = 0; i < 4; i++)
        t[y + 8 * i][x] = W[(size_t)(bx + y + 8 * i) * N + by + x];
    __syncthreads();
#pragma unroll
    for (int i = 0; i < 4; i++) {
        float v = t[x][y + 8 * i];
        __nv_bfloat16 h = __float2bfloat16(v);
        size_t o = (size_t)(by + y + 8 * i) * K + bx + x;
        hiT[o] = h;
        loT[o] = __float2bfloat16(v - __bfloat162float(h));
    }
}

__global__ void exp_convert_kernel(const float* __restrict__ sim,
                                   const float* __restrict__ rmax,
                                   const float* __restrict__ cmax,
                                   __nv_bfloat16* __restrict__ Pr,
                                   __nv_bfloat16* __restrict__ Pc) {
    __shared__ float t[32][33];
    const int bx = blockIdx.x * 32, by = blockIdx.y * 32;
    const int x = threadIdx.x, y = threadIdx.y;  // (32, 8)
    const float cm = cmax[bx + x];
#pragma unroll
    for (int i = 0; i < 4; i++) {
        const int r = by + y + 8 * i;
        float v = sim[(size_t)r * NN + bx + x];
        Pr[(size_t)r * NN + bx + x] = __float2bfloat16(__expf(v - rmax[r]));
        t[y + 8 * i][x] = __expf(v - cm);
    }
    __syncthreads();
#pragma unroll
    for (int i = 0; i < 4; i++)
        Pc[(size_t)(bx + y + 8 * i) * NN + by + x] = __float2bfloat16(t[x][y + 8 * i]);
}

// ---------------------------------------------------------------------------
// Degree / normalization, GCN scatter
// ---------------------------------------------------------------------------
__global__ void fill1_kernel(float* d, int n) {
    int i = blockIdx.x * 256 + threadIdx.x;
    if (i < n) d[i] = 1.0f;
}
__global__ void degcnt_kernel(const int* __restrict__ dst, int E, float* deg) {
    int e = blockIdx.x * 256 + threadIdx.x;
    if (e < E) atomicAdd(&deg[dst[e]], 1.0f);
}
__global__ void rsqrt_kernel(float* d, int n) {
    int i = blockIdx.x * 256 + threadIdx.x;
    if (i < n) d[i] = rsqrtf(d[i]);
}
__global__ void gcn_self_kernel(const float* __restrict__ h,
                                const float* __restrict__ dinv,
                                float* __restrict__ c) {
    int idx = blockIdx.x * 256 + threadIdx.x;
    int v = idx >> 8;
    float dv = dinv[v];
    c[idx] = dv * dv * h[idx];
}
__global__ void gcn_scatter_kernel(const int* __restrict__ src,
                                   const int* __restrict__ dst,
                                   const float* __restrict__ dinv,
                                   const float* __restrict__ h,
                                   float* __restrict__ c) {
    int e = blockIdx.x;
    int s = src[e], d = dst[e];
    float w = dinv[s] * dinv[d];
    atomicAdd(&c[(size_t)d * HDIM + threadIdx.x],
              w * h[(size_t)s * HDIM + threadIdx.x]);
}

// ---------------------------------------------------------------------------
// Online softmax statistics over fp32 sim
// ---------------------------------------------------------------------------
__device__ __forceinline__ void sm_combine(float& m, float& s, float m2, float s2) {
    float M = fmaxf(m, m2);
    s = s * __expf(m - M) + s2 * __expf(m2 - M);
    m = M;
}
__global__ void rowstats_kernel(const float* __restrict__ sim,
                                float* __restrict__ rmax, float* __restrict__ rsum) {
    const int row = blockIdx.x;
    const float* p = sim + (size_t)row * NN;
    float m = -1e30f, s = 0.f;
    for (int c = threadIdx.x; c < NN; c += 256) {
        float x = p[c];
        if (x > m) { s = s * __expf(m - x) + 1.f; m = x; }
        else       { s += __expf(x - m); }
    }
#pragma unroll
    for (int o = 16; o > 0; o >>= 1) {
        float m2 = __shfl_xor_sync(0xffffffffu, m, o);
        float s2 = __shfl_xor_sync(0xffffffffu, s, o);
        sm_combine(m, s, m2, s2);
    }
    __shared__ float sm[8], ss[8];
    int w = threadIdx.x >> 5, l = threadIdx.x & 31;
    if (l == 0) { sm[w] = m; ss[w] = s; }
    __syncthreads();
    if (threadIdx.x == 0) {
        m = sm[0]; s = ss[0];
        for (int i = 1; i < 8; i++) sm_combine(m, s, sm[i], ss[i]);
        rmax[row] = m; rsum[row] = s;
    }
}
__global__ void colstats_band_kernel(const float* __restrict__ sim,
                                     float* __restrict__ band) {
    const int col = blockIdx.x * 32 + threadIdx.x;
    const int y = threadIdx.y;
    const int r0 = blockIdx.y * (NN / 8);
    float m = -1e30f, s = 0.f;
    for (int r = r0 + y; r < r0 + NN / 8; r += 8) {
        float x = sim[(size_t)r * NN + col];
        if (x > m) { s = s * __expf(m - x) + 1.f; m = x; }
        else       { s += __expf(x - m); }
    }
    __shared__ float sm[8][32], ss[8][32];
    sm[y][threadIdx.x] = m; ss[y][threadIdx.x] = s;
    __syncthreads();
    if (y == 0) {
        for (int i = 1; i < 8; i++) sm_combine(m, s, sm[i][threadIdx.x], ss[i][threadIdx.x]);
        band[((size_t)blockIdx.y * NN + col) * 2]     = m;
        band[((size_t)blockIdx.y * NN + col) * 2 + 1] = s;
    }
}
__global__ void colmerge_kernel(const float* __restrict__ band,
                                float* __restrict__ cmax, float* __restrict__ csum) {
    int col = blockIdx.x * 256 + threadIdx.x;
    float m = band[(size_t)col * 2], s = band[(size_t)col * 2 + 1];
#pragma unroll
    for (int b = 1; b < 8; b++)
        sm_combine(m, s, band[((size_t)b * NN + col) * 2],
                         band[((size_t)b * NN + col) * 2 + 1]);
    cmax[col] = m; csum[col] = s;
}

// ---------------------------------------------------------------------------
// cat = [c | f | f - att] -> bf16 hi/lo (att rows have stride din)
// ---------------------------------------------------------------------------
__global__ void cat_split_kernel(const float* __restrict__ c, const float* __restrict__ f,
                                 const float* __restrict__ att,
                                 __nv_bfloat16* __restrict__ cath,
                                 __nv_bfloat16* __restrict__ catl, int din) {
    const int catw = HDIM + 2 * din;
    size_t idx = (size_t)blockIdx.x * 256 + threadIdx.x;
    if (idx >= (size_t)NN * catw) return;
    int r = (int)(idx / catw), col = (int)(idx % catw);
    float v;
    if (col < HDIM)            v = c[(size_t)r * HDIM + col];
    else if (col < HDIM + din) v = f[(size_t)r * din + (col - HDIM)];
    else {
        int cc = col - HDIM - din;
        v = f[(size_t)r * din + cc] - att[(size_t)r * din + cc];
    }
    __nv_bfloat16 h = __float2bfloat16(v);
    cath[idx] = h;
    catl[idx] = __float2bfloat16(v - __bfloat162float(h));
}

// ---------------------------------------------------------------------------
// Gated readout + NTN tail
// ---------------------------------------------------------------------------
__global__ void zero_kernel(float* p, int n) {
    int i = blockIdx.x * 256 + threadIdx.x;
    if (i < n) p[i] = 0.f;
}
__global__ void preduce_kernel(const float* __restrict__ z,
                               const float* __restrict__ f,
                               float* __restrict__ p) {
    const int c = threadIdx.x;
    const int r0 = blockIdx.x * 64;
    float acc = 0.f;
    for (int r = r0; r < r0 + 64; r++)
        acc += z[(size_t)r * HDIM + c] * f[(size_t)r * HDIM + c];
    atomicAdd(&p[c], acc);
}
__global__ void ntn1_kernel(const float* __restrict__ p1,
                            const float* __restrict__ W,
                            float* __restrict__ tmp) {
    int g = blockIdx.x * 256 + threadIdx.x;
    float acc = 0.f;
    for (int i = 0; i < HDIM; i++) acc += p1[i] * W[(size_t)i * 8192 + g];
    tmp[g] = acc;
}
__global__ void tail_kernel(const float* __restrict__ p1, const float* __restrict__ p2,
                            const float* __restrict__ tmp,
                            const float* __restrict__ Wb, const float* __restrict__ tnb,
                            const float* __restrict__ fc1W, const float* __restrict__ fc1b,
                            const float* __restrict__ scW, const float* __restrict__ scb,
                            const float* __restrict__ avgv,
                            float* __restrict__ out, int out_size) {
    __shared__ float ntn[32];
    __shared__ float sv[16];
    const int t = threadIdx.x;
    float acc = tnb[t];
    for (int j = 0; j < HDIM; j++) acc += tmp[j * 32 + t] * p2[j];
    for (int k = 0; k < HDIM; k++)
        acc += Wb[t * 512 + k] * p1[k] + Wb[t * 512 + HDIM + k] * p2[k];
    ntn[t] = fmaxf(acc, 0.f);
    __syncthreads();
    if (t < 16) {
        float a = fc1b[t];
        for (int q = 0; q < 32; q++) a += ntn[q] * fc1W[q * 16 + t];
        sv[t] = tanhf(a);
    }
    __syncthreads();
    if (t == 0) {
        float a = scb[0];
        for (int q = 0; q < 16; q++) a += sv[q] * scW[q];
        float sc = 1.f / (1.f + expf(-a));
        out[0] = sc;
        if (out_size > 1) out[1] = -logf(sc) * avgv[0];
    }
}

// ---------------------------------------------------------------------------
// Host launcher
// ---------------------------------------------------------------------------
extern "C" void kernel_launch(void* const* d_in, const int* in_sizes, int n_in,
                              void* d_out, int out_size)
{
    const float* f1in  = (const float*)d_in[0];
    const float* f2in  = (const float*)d_in[1];
    const int*   ei1   = (const int*)d_in[2];
    const int*   ei2   = (const int*)d_in[3];
    const float* avgv  = (const float*)d_in[4];
    const float* gcnW[3] = {(const float*)d_in[5], (const float*)d_in[8],  (const float*)d_in[11]};
    const float* updW[3] = {(const float*)d_in[6], (const float*)d_in[9],  (const float*)d_in[12]};
    const float* updb[3] = {(const float*)d_in[7], (const float*)d_in[10], (const float*)d_in[13]};
    const float* gatedW = (const float*)d_in[14];
    const float* gatedb = (const float*)d_in[15];
    const float* tnW  = (const float*)d_in[16];
    const float* tnWb = (const float*)d_in[17];
    const float* tnb  = (const float*)d_in[18];
    const float* fc1W = (const float*)d_in[19];
    const float* fc1b = (const float*)d_in[20];
    const float* scW  = (const float*)d_in[21];
    const float* scb  = (const float*)d_in[22];

    const int E = in_sizes[2] / 2;

    float *sim, *h1, *h2, *c1, *c2, *att1, *att2, *fa1, *fa2, *fb1, *fb2;
    float *rmax, *rsum, *cmax, *csum, *bandp, *dinv1, *dinv2, *pvec, *tmp;
    __nv_bfloat16 *Pr, *Pc, *fh1, *fl1, *fh2, *fl2, *f1T, *f2T;
    __nv_bfloat16 *cath1, *catl1, *cath2, *catl2;
    __nv_bfloat16 *gcnWTh, *gcnWTl, *updWTh, *updWTl, *gatedWTh, *gatedWTl;
    cudaGetSymbolAddress((void**)&sim,  g_sim);
    cudaGetSymbolAddress((void**)&Pr,   g_Pr);
    cudaGetSymbolAddress((void**)&Pc,   g_Pc);
    cudaGetSymbolAddress((void**)&fh1,  g_fh1);
    cudaGetSymbolAddress((void**)&fl1,  g_fl1);
    cudaGetSymbolAddress((void**)&fh2,  g_fh2);
    cudaGetSymbolAddress((void**)&fl2,  g_fl2);
    cudaGetSymbolAddress((void**)&f1T,  g_f1T);
    cudaGetSymbolAddress((void**)&f2T,  g_f2T);
    cudaGetSymbolAddress((void**)&h1,   g_h1);
    cudaGetSymbolAddress((void**)&h2,   g_h2);
    cudaGetSymbolAddress((void**)&c1,   g_c1);
    cudaGetSymbolAddress((void**)&c2,   g_c2);
    cudaGetSymbolAddress((void**)&att1, g_att1);
    cudaGetSymbolAddress((void**)&att2, g_att2);
    cudaGetSymbolAddress((void**)&fa1,  g_fa1);
    cudaGetSymbolAddress((void**)&fa2,  g_fa2);
    cudaGetSymbolAddress((void**)&fb1,  g_fb1);
    cudaGetSymbolAddress((void**)&fb2,  g_fb2);
    cudaGetSymbolAddress((void**)&cath1, g_cath1);
    cudaGetSymbolAddress((void**)&catl1, g_catl1);
    cudaGetSymbolAddress((void**)&cath2, g_cath2);
    cudaGetSymbolAddress((void**)&catl2, g_catl2);
    cudaGetSymbolAddress((void**)&rmax, g_rmax);
    cudaGetSymbolAddress((void**)&rsum, g_rsum);
    cudaGetSymbolAddress((void**)&cmax, g_cmax);
    cudaGetSymbolAddress((void**)&csum, g_csum);
    cudaGetSymbolAddress((void**)&bandp, g_band);
    cudaGetSymbolAddress((void**)&dinv1, g_dinv1);
    cudaGetSymbolAddress((void**)&dinv2, g_dinv2);
    cudaGetSymbolAddress((void**)&pvec, g_p);
    cudaGetSymbolAddress((void**)&tmp,  g_tmp);
    cudaGetSymbolAddress((void**)&gcnWTh, g_gcnWT_h);
    cudaGetSymbolAddress((void**)&gcnWTl, g_gcnWT_l);
    cudaGetSymbolAddress((void**)&updWTh, g_updWT_h);
    cudaGetSymbolAddress((void**)&updWTl, g_updWT_l);
    cudaGetSymbolAddress((void**)&gatedWTh, g_gatedWT_h);
    cudaGetSymbolAddress((void**)&gatedWTl, g_gatedWT_l);

    const int SMEM_SPLIT = 2 * (2 * A_TB + 2 * B_TB);  // 98304
    const int SMEM_PLAIN = 2 * (A_TB + B_TB);          // 49152
    cudaFuncSetAttribute(mma_gemm<1, 0, 0>, cudaFuncAttributeMaxDynamicSharedMemorySize, SMEM_SPLIT);
    cudaFuncSetAttribute(mma_gemm<0, 1, 1>, cudaFuncAttributeMaxDynamicSharedMemorySize, SMEM_PLAIN);

    // --- one-time weight transpose + hi/lo split ---
    const dim3 wtb(32, 8);
    for (int L = 0; L < 3; L++) {
        const int dk = (L == 0) ? DIN0 : HDIM;
        const int cw = HDIM + 2 * dk;
        wtsplit_kernel<<<dim3(dk / 32, HDIM / 32), wtb>>>(
            gcnW[L], gcnWTh + L * HDIM * HDIM, gcnWTl + L * HDIM * HDIM, dk, HDIM);
        wtsplit_kernel<<<dim3(cw / 32, HDIM / 32), wtb>>>(
            updW[L], updWTh + L * HDIM * 768, updWTl + L * HDIM * 768, cw, HDIM);
    }
    wtsplit_kernel<<<dim3(HDIM / 32, HDIM / 32), wtb>>>(gatedW, gatedWTh, gatedWTl, HDIM, HDIM);

    // --- degree normalization ---
    fill1_kernel<<<(NN + 255) / 256, 256>>>(dinv1, NN);
    fill1_kernel<<<(NN + 255) / 256, 256>>>(dinv2, NN);
    degcnt_kernel<<<(E + 255) / 256, 256>>>(ei1 + E, E, dinv1);
    degcnt_kernel<<<(E + 255) / 256, 256>>>(ei2 + E, E, dinv2);
    rsqrt_kernel<<<(NN + 255) / 256, 256>>>(dinv1, NN);
    rsqrt_kernel<<<(NN + 255) / 256, 256>>>(dinv2, NN);

    const float* f1p = f1in;
    const float* f2p = f2in;
    int din = DIN0;

    for (int L = 0; L < 3; L++) {
        float* o1 = (L == 1) ? fa1 : fb1;
        float* o2 = (L == 1) ? fa2 : fb2;
        const __nv_bfloat16* gWh = gcnWTh + L * HDIM * HDIM;
        const __nv_bfloat16* gWl = gcnWTl + L * HDIM * HDIM;
        const __nv_bfloat16* uWh = updWTh + L * HDIM * 768;
        const __nv_bfloat16* uWl = updWTl + L * HDIM * 768;

        // zero att accumulators (split-K atomic epilogue)
        zero_kernel<<<NN * din / 256, 256>>>(att1, NN * din);
        zero_kernel<<<NN * din / 256, 256>>>(att2, NN * din);

        // bf16 forms of features
        split_bf16_kernel<<<NN * din / 256, 256>>>(f1p, fh1, fl1, NN * din);
        split_bf16_kernel<<<NN * din / 256, 256>>>(f2p, fh2, fl2, NN * din);
        transpose_bf16_kernel<<<dim3(din / 32, NN / 32), dim3(32, 8)>>>(f1p, f1T, din);
        transpose_bf16_kernel<<<dim3(din / 32, NN / 32), dim3(32, 8)>>>(f2p, f2T, din);

        // GCN: h = f @ Wg (split bf16 tensor)
        mma_gemm<1, 0, 0><<<dim3(HDIM / 64, NN / 128), 256, SMEM_SPLIT>>>(
            fh1, fl1, gWh, gWl, h1, HDIM, din, nullptr, nullptr, 0);
        mma_gemm<1, 0, 0><<<dim3(HDIM / 64, NN / 128), 256, SMEM_SPLIT>>>(
            fh2, fl2, gWh, gWl, h2, HDIM, din, nullptr, nullptr, 0);
        gcn_self_kernel<<<NN * HDIM / 256, 256>>>(h1, dinv1, c1);
        gcn_self_kernel<<<NN * HDIM / 256, 256>>>(h2, dinv2, c2);
        gcn_scatter_kernel<<<E, 256>>>(ei1, ei1 + E, dinv1, h1, c1);
        gcn_scatter_kernel<<<E, 256>>>(ei2, ei2 + E, dinv2, h2, c2);

        // sim = f1 @ f2^T (split bf16 => fp32-grade)
        mma_gemm<1, 0, 0><<<dim3(NN / 64, NN / 128), 256, SMEM_SPLIT>>>(
            fh1, fl1, fh2, fl2, sim, NN, din, nullptr, nullptr, 0);

        // softmax statistics (fp32): row stats + banded col stats
        rowstats_kernel<<<NN, 256>>>(sim, rmax, rsum);
        colstats_band_kernel<<<dim3(NN / 32, 8), dim3(32, 8)>>>(sim, bandp);
        colmerge_kernel<<<NN / 256, 256>>>(bandp, cmax, csum);

        // P matrices (bf16)
        exp_convert_kernel<<<dim3(NN / 32, NN / 32), dim3(32, 8)>>>(sim, rmax, cmax, Pr, Pc);

        // att1 = softmax_row(sim) @ f2 ; att2 = softmax_col(sim)^T @ f1
        // split-K for grid parallelism (K = NN = 8192 -> 512 blocks each)
        const int zk = (din == DIN0) ? 4 : 2;
        mma_gemm<0, 1, 1><<<dim3(din / 64, NN / 128, zk), 256, SMEM_PLAIN>>>(
            Pr, nullptr, f2T, nullptr, att1, din, NN, rsum, nullptr, 0);
        mma_gemm<0, 1, 1><<<dim3(din / 64, NN / 128, zk), 256, SMEM_PLAIN>>>(
            Pc, nullptr, f1T, nullptr, att2, din, NN, csum, nullptr, 0);

        // cat (bf16 hi/lo) + update GEMM (+tanh except last layer)
        const int catw = HDIM + 2 * din;
        const int nel = NN * catw;
        cat_split_kernel<<<(nel + 255) / 256, 256>>>(c1, f1p, att1, cath1, catl1, din);
        cat_split_kernel<<<(nel + 255) / 256, 256>>>(c2, f2p, att2, cath2, catl2, din);
        const int act = (L == 2) ? 0 : 1;
        mma_gemm<1, 0, 0><<<dim3(HDIM / 64, NN / 128), 256, SMEM_SPLIT>>>(
            cath1, catl1, uWh, uWl, o1, HDIM, catw, nullptr, updb[L], act);
        mma_gemm<1, 0, 0><<<dim3(HDIM / 64, NN / 128), 256, SMEM_SPLIT>>>(
            cath2, catl2, uWh, uWl, o2, HDIM, catw, nullptr, updb[L], act);

        f1p = o1; f2p = o2; din = HDIM;
    }

    // --- gated readout (split bf16 tensor + sigmoid epilogue) ---
    split_bf16_kernel<<<NN * HDIM / 256, 256>>>(f1p, fh1, fl1, NN * HDIM);
    split_bf16_kernel<<<NN * HDIM / 256, 256>>>(f2p, fh2, fl2, NN * HDIM);
    mma_gemm<1, 0, 0><<<dim3(HDIM / 64, NN / 128), 256, SMEM_SPLIT>>>(
        fh1, fl1, gatedWTh, gatedWTl, h1, HDIM, HDIM, nullptr, gatedb, 2);
    mma_gemm<1, 0, 0><<<dim3(HDIM / 64, NN / 128), 256, SMEM_SPLIT>>>(
        fh2, fl2, gatedWTh, gatedWTl, h2, HDIM, HDIM, nullptr, gatedb, 2);
    zero_kernel<<<2, 256>>>(pvec, 2 * HDIM);
    preduce_kernel<<<NN / 64, 256>>>(h1, f1p, pvec);
    preduce_kernel<<<NN / 64, 256>>>(h2, f2p, pvec + HDIM);

    // --- NTN + head ---
    ntn1_kernel<<<32, 256>>>(pvec, tnW, tmp);
    tail_kernel<<<1, 32>>>(pvec, pvec + HDIM, tmp, tnWb, tnb,
                           fc1W, fc1b, scW, scb, avgv, (float*)d_out, out_size);
}

// round 17
// speedup vs baseline: 1.1704x; 1.1210x over previous
#include <cuda_runtime.h>
#include <cuda_bf16.h>
#include <math.h>
#include <stddef.h>
#include <stdint.h>

// ---------------------------------------------------------------------------
// Problem constants
// ---------------------------------------------------------------------------
#define NN    8192     // nodes per graph
#define HDIM  256      // hidden dim
#define DIN0  128      // input feature dim
#define EDGES 131072   // edges per graph (problem constant)

// ---------------------------------------------------------------------------
// Static device scratch (no allocations allowed)
// ---------------------------------------------------------------------------
__device__ float g_sim[(size_t)NN * NN];            // 256 MB fp32 similarity
__device__ __nv_bfloat16 g_Pr[(size_t)NN * NN];     // exp(sim - rmax) bf16
__device__ __nv_bfloat16 g_Pc[(size_t)NN * NN];     // exp(sim^T - cmax) bf16
__device__ __nv_bfloat16 g_fh1[NN * HDIM], g_fl1[NN * HDIM];
__device__ __nv_bfloat16 g_fh2[NN * HDIM], g_fl2[NN * HDIM];
__device__ __nv_bfloat16 g_f1T[HDIM * NN], g_f2T[HDIM * NN];
__device__ float g_h1[NN * HDIM], g_h2[NN * HDIM];
__device__ float g_c1[NN * HDIM], g_c2[NN * HDIM];
__device__ float g_att1[NN * HDIM], g_att2[NN * HDIM];
__device__ float g_fa1[NN * HDIM], g_fa2[NN * HDIM];
__device__ float g_fb1[NN * HDIM], g_fb2[NN * HDIM];
__device__ __nv_bfloat16 g_cath1[NN * 768], g_catl1[NN * 768];
__device__ __nv_bfloat16 g_cath2[NN * 768], g_catl2[NN * 768];
__device__ float g_rmax[NN], g_rsum[NN], g_cmax[NN], g_csum[NN];
__device__ float g_band[8 * NN * 2];                // per-band col (max,sum) partials
__device__ float g_dinv1[NN], g_dinv2[NN];
__device__ float g_p[2 * HDIM];
__device__ float g_tmp[HDIM * 32];
// CSR for the two graphs (edges identical across layers)
__device__ int g_rs1[NN + 1], g_rs2[NN + 1];
__device__ int g_csr1[EDGES], g_csr2[EDGES];
__device__ int g_degi[NN], g_cur[NN];
// transposed + hi/lo split weights (bf16), done once per launch
__device__ __nv_bfloat16 g_gcnWT_h[3][HDIM * HDIM], g_gcnWT_l[3][HDIM * HDIM];
__device__ __nv_bfloat16 g_updWT_h[3][HDIM * 768], g_updWT_l[3][HDIM * 768];
__device__ __nv_bfloat16 g_gatedWT_h[HDIM * HDIM], g_gatedWT_l[HDIM * HDIM];

// ---------------------------------------------------------------------------
// mma.sync helpers (portable tensor-core path, valid on base sm_103 target)
// ---------------------------------------------------------------------------
__device__ __forceinline__ uint32_t smem_u32(const void* p) {
    uint32_t a;
    asm("{ .reg .u64 t; cvta.to.shared.u64 t, %1; cvt.u32.u64 %0, t; }"
        : "=r"(a) : "l"(p));
    return a;
}
__device__ __forceinline__ void ldmx4(uint32_t* r, uint32_t addr) {
    asm volatile("ldmatrix.sync.aligned.m8n8.x4.shared.b16 {%0,%1,%2,%3}, [%4];"
        : "=r"(r[0]), "=r"(r[1]), "=r"(r[2]), "=r"(r[3]) : "r"(addr));
}
__device__ __forceinline__ void mma16816(float* d, const uint32_t* a, const uint32_t* b) {
    asm volatile("mma.sync.aligned.m16n8k16.row.col.f32.bf16.bf16.f32 "
        "{%0,%1,%2,%3}, {%4,%5,%6,%7}, {%8,%9}, {%0,%1,%2,%3};"
        : "+f"(d[0]), "+f"(d[1]), "+f"(d[2]), "+f"(d[3])
        : "r"(a[0]), "r"(a[1]), "r"(a[2]), "r"(a[3]), "r"(b[0]), "r"(b[1]));
}
__device__ __forceinline__ void cp16(uint32_t dst, const void* src) {
    asm volatile("cp.async.cg.shared.global [%0], [%1], 16;" :: "r"(dst), "l"(src));
}

// ---------------------------------------------------------------------------
// bf16 tensor-core GEMM (128x64 tile): C[M,N] = A @ B^T (both K-major bf16)
//   SPLIT=1 : hi/lo pairs; D = Ah*Bh + Ah*Bl + Al*Bh (~fp32)
//   SCALE=1 : result row m multiplied by 1/vsum[m]
//   ATOMIC=1: accumulate into C via atomicAdd (split-K; C pre-zeroed;
//             blockIdx.z selects the K slice; bias must be null)
// 8 warps (4x2), warp tile 32x32, K chunks of 64, 2-stage cp.async.
// ---------------------------------------------------------------------------
#define BKCH 64
#define A_TB 16384   // 128 rows * 128B
#define B_TB 8192    // 64 rows * 128B

template<int SPLIT, int SCALE, int ATOMIC>
__global__ void __launch_bounds__(256)
mma_gemm(const __nv_bfloat16* __restrict__ Ah, const __nv_bfloat16* __restrict__ Al,
         const __nv_bfloat16* __restrict__ Bh, const __nv_bfloat16* __restrict__ Bl,
         float* __restrict__ C, int N, int K, const float* __restrict__ vsum,
         const float* __restrict__ bias, int act)
{
    extern __shared__ char smem[];
    const uint32_t sb = smem_u32(smem);
    const int tid = threadIdx.x;
    const int wid = tid >> 5, lane = tid & 31;
    const int warp_m = wid & 3, warp_n = wid >> 2;      // 4 x 2 warp grid
    const int m0 = blockIdx.y * 128, n0 = blockIdx.x * 64;
    const uint32_t BUFB = SPLIT ? (2 * A_TB + 2 * B_TB) : (A_TB + B_TB);
    const uint32_t BOFF = SPLIT ? 2 * A_TB : A_TB;

    auto issue = [&](int ch, int buf) {
        const uint32_t base = sb + buf * BUFB;
#pragma unroll
        for (int g = 0; g < 4; g++) {          // A tile: 128 rows x 8 x 16B
            const int idx = tid * 4 + g;
            const int row = idx >> 3, c16 = idx & 7;
            uint32_t off = row * 128 + c16 * 16;
            uint32_t sw = off ^ ((off >> 3) & 0x70);
            const char* s = (const char*)(Ah + (size_t)(m0 + row) * K + ch * BKCH) + c16 * 16;
            cp16(base + sw, s);
            if (SPLIT) {
                const char* sl = (const char*)(Al + (size_t)(m0 + row) * K + ch * BKCH) + c16 * 16;
                cp16(base + A_TB + sw, sl);
            }
        }
#pragma unroll
        for (int g = 0; g < 2; g++) {          // B tile: 64 rows x 8 x 16B
            const int idx = tid * 2 + g;
            const int row = idx >> 3, c16 = idx & 7;
            uint32_t off = row * 128 + c16 * 16;
            uint32_t sw = off ^ ((off >> 3) & 0x70);
            const char* s = (const char*)(Bh + (size_t)(n0 + row) * K + ch * BKCH) + c16 * 16;
            cp16(base + BOFF + sw, s);
            if (SPLIT) {
                const char* sl = (const char*)(Bl + (size_t)(n0 + row) * K + ch * BKCH) + c16 * 16;
                cp16(base + BOFF + B_TB + sw, sl);
            }
        }
        asm volatile("cp.async.commit_group;" ::: "memory");
    };

    float acc[2][4][4];
#pragma unroll
    for (int i = 0; i < 2; i++)
#pragma unroll
        for (int j = 0; j < 4; j++)
#pragma unroll
            for (int q = 0; q < 4; q++) acc[i][j][q] = 0.f;

    const int nch = (K / BKCH) / gridDim.z;
    const int ch0 = blockIdx.z * nch;

    issue(ch0, 0);
    for (int c = 0; c < nch; c++) {
        if (c + 1 < nch) {
            issue(ch0 + c + 1, (c + 1) & 1);
            asm volatile("cp.async.wait_group 1;" ::: "memory");
        } else {
            asm volatile("cp.async.wait_group 0;" ::: "memory");
        }
        __syncthreads();
        const uint32_t base = sb + (c & 1) * BUFB;
        const uint32_t aB = base, alB = base + A_TB;
        const uint32_t bB = base + BOFF, blB = base + BOFF + B_TB;
#pragma unroll
        for (int kk = 0; kk < 4; kk++) {
            uint32_t ah[2][4], al[2][4];
#pragma unroll
            for (int mt = 0; mt < 2; mt++) {
                const int row = warp_m * 32 + mt * 16 + (lane & 7) + ((lane >> 3) & 1) * 8;
                uint32_t off = row * 128 + kk * 32 + (lane >> 4) * 16;
                uint32_t sw = off ^ ((off >> 3) & 0x70);
                ldmx4(ah[mt], aB + sw);
                if (SPLIT) ldmx4(al[mt], alB + sw);
            }
            uint32_t bh[4][2], bl[4][2];
#pragma unroll
            for (int np = 0; np < 2; np++) {
                const int row = warp_n * 32 + np * 16 + (lane & 7) + ((lane >> 3) & 1) * 8;
                uint32_t off = row * 128 + kk * 32 + (lane >> 4) * 16;
                uint32_t sw = off ^ ((off >> 3) & 0x70);
                uint32_t r[4];
                ldmx4(r, bB + sw);
                bh[np * 2][0] = r[0]; bh[np * 2][1] = r[2];
                bh[np * 2 + 1][0] = r[1]; bh[np * 2 + 1][1] = r[3];
                if (SPLIT) {
                    ldmx4(r, blB + sw);
                    bl[np * 2][0] = r[0]; bl[np * 2][1] = r[2];
                    bl[np * 2 + 1][0] = r[1]; bl[np * 2 + 1][1] = r[3];
                }
            }
#pragma unroll
            for (int mt = 0; mt < 2; mt++)
#pragma unroll
                for (int nt = 0; nt < 4; nt++) {
                    mma16816(acc[mt][nt], ah[mt], bh[nt]);
                    if (SPLIT) {
                        mma16816(acc[mt][nt], ah[mt], bl[nt]);
                        mma16816(acc[mt][nt], al[mt], bh[nt]);
                    }
                }
        }
        __syncthreads();
    }

    const int r = lane >> 2, cg = (lane & 3) * 2;
#pragma unroll
    for (int mt = 0; mt < 2; mt++) {
        const int mrow = m0 + warp_m * 32 + mt * 16 + r;
        const float s0 = SCALE ? (1.f / vsum[mrow]) : 1.f;
        const float s8 = SCALE ? (1.f / vsum[mrow + 8]) : 1.f;
#pragma unroll
        for (int nt = 0; nt < 4; nt++) {
            const int ncol = n0 + warp_n * 32 + nt * 8 + cg;
            if (ATOMIC) {
                atomicAdd(C + (size_t)mrow * N + ncol,           acc[mt][nt][0] * s0);
                atomicAdd(C + (size_t)mrow * N + ncol + 1,       acc[mt][nt][1] * s0);
                atomicAdd(C + (size_t)(mrow + 8) * N + ncol,     acc[mt][nt][2] * s8);
                atomicAdd(C + (size_t)(mrow + 8) * N + ncol + 1, acc[mt][nt][3] * s8);
            } else {
                float b0 = 0.f, b1 = 0.f;
                if (bias) { b0 = bias[ncol]; b1 = bias[ncol + 1]; }
                float4 v;
                v.x = acc[mt][nt][0] * s0 + b0;
                v.y = acc[mt][nt][1] * s0 + b1;
                v.z = acc[mt][nt][2] * s8 + b0;
                v.w = acc[mt][nt][3] * s8 + b1;
                if (act == 1) {
                    v.x = tanhf(v.x); v.y = tanhf(v.y); v.z = tanhf(v.z); v.w = tanhf(v.w);
                } else if (act == 2) {
                    v.x = 1.f / (1.f + __expf(-v.x)); v.y = 1.f / (1.f + __expf(-v.y));
                    v.z = 1.f / (1.f + __expf(-v.z)); v.w = 1.f / (1.f + __expf(-v.w));
                }
                *(float2*)(C + (size_t)mrow * N + ncol) = make_float2(v.x, v.y);
                *(float2*)(C + (size_t)(mrow + 8) * N + ncol) = make_float2(v.z, v.w);
            }
        }
    }
}

// ---------------------------------------------------------------------------
// Conversions
// ---------------------------------------------------------------------------
__global__ void split_bf16_kernel(const float* __restrict__ f,
                                  __nv_bfloat16* __restrict__ hi,
                                  __nv_bfloat16* __restrict__ lo, int n) {
    int i = blockIdx.x * 256 + threadIdx.x;
    if (i >= n) return;
    float x = f[i];
    __nv_bfloat16 h = __float2bfloat16(x);
    hi[i] = h;
    lo[i] = __float2bfloat16(x - __bfloat162float(h));
}

__global__ void transpose_bf16_kernel(const float* __restrict__ f,
                                      __nv_bfloat16* __restrict__ fT, int din) {
    __shared__ float t[32][33];
    const int bx = blockIdx.x * 32, by = blockIdx.y * 32;
    const int x = threadIdx.x, y = threadIdx.y;  // (32, 8)
#pragma unroll
    for (int i = 0; i < 4; i++)
        t[y + 8 * i][x] = f[(size_t)(by + y + 8 * i) * din + bx + x];
    __syncthreads();
#pragma unroll
    for (int i = 0; i < 4; i++)
        fT[(size_t)(bx + y + 8 * i) * NN + by + x] = __float2bfloat16(t[x][y + 8 * i]);
}

__global__ void wtsplit_kernel(const float* __restrict__ W,
                               __nv_bfloat16* __restrict__ hiT,
                               __nv_bfloat16* __restrict__ loT, int K, int N) {
    __shared__ float t[32][33];
    const int bx = blockIdx.x * 32, by = blockIdx.y * 32;   // bx: K, by: N
    const int x = threadIdx.x, y = threadIdx.y;
#pragma unroll
    for (int i = 0; i < 4; i++)
        t[y + 8 * i][x] = W[(size_t)(bx + y + 8 * i) * N + by + x];
    __syncthreads();
#pragma unroll
    for (int i = 0; i < 4; i++) {
        float v = t[x][y + 8 * i];
        __nv_bfloat16 h = __float2bfloat16(v);
        size_t o = (size_t)(by + y + 8 * i) * K + bx + x;
        hiT[o] = h;
        loT[o] = __float2bfloat16(v - __bfloat162float(h));
    }
}

__global__ void exp_convert_kernel(const float* __restrict__ sim,
                                   const float* __restrict__ rmax,
                                   const float* __restrict__ cmax,
                                   __nv_bfloat16* __restrict__ Pr,
                                   __nv_bfloat16* __restrict__ Pc) {
    __shared__ float t[32][33];
    const int bx = blockIdx.x * 32, by = blockIdx.y * 32;
    const int x = threadIdx.x, y = threadIdx.y;  // (32, 8)
    const float cm = cmax[bx + x];
#pragma unroll
    for (int i = 0; i < 4; i++) {
        const int r = by + y + 8 * i;
        float v = sim[(size_t)r * NN + bx + x];
        Pr[(size_t)r * NN + bx + x] = __float2bfloat16(__expf(v - rmax[r]));
        t[y + 8 * i][x] = __expf(v - cm);
    }
    __syncthreads();
#pragma unroll
    for (int i = 0; i < 4; i++)
        Pc[(size_t)(bx + y + 8 * i) * NN + by + x] = __float2bfloat16(t[x][y + 8 * i]);
}

// ---------------------------------------------------------------------------
// Degree / normalization + CSR build + SpMM aggregation
// ---------------------------------------------------------------------------
__global__ void fill1_kernel(float* d, int n) {
    int i = blockIdx.x * 256 + threadIdx.x;
    if (i < n) d[i] = 1.0f;
}
__global__ void zeroint_kernel(int* d, int n) {
    int i = blockIdx.x * 256 + threadIdx.x;
    if (i < n) d[i] = 0;
}
__global__ void degcnt_kernel(const int* __restrict__ dst, int E, float* deg) {
    int e = blockIdx.x * 256 + threadIdx.x;
    if (e < E) atomicAdd(&deg[dst[e]], 1.0f);
}
__global__ void degint_kernel(const int* __restrict__ dst, int E, int* deg) {
    int e = blockIdx.x * 256 + threadIdx.x;
    if (e < E) atomicAdd(&deg[dst[e]], 1);
}
__global__ void rsqrt_kernel(float* d, int n) {
    int i = blockIdx.x * 256 + threadIdx.x;
    if (i < n) d[i] = rsqrtf(d[i]);
}
// Exclusive scan of deg[NN] -> rs[NN+1], single block of 1024 threads (8 each)
__global__ void __launch_bounds__(1024)
scan_kernel(const int* __restrict__ deg, int* __restrict__ rs) {
    __shared__ int ts[1024];
    const int t = threadIdx.x;
    const int base = t * 8;
    int loc[8], s = 0;
#pragma unroll
    for (int i = 0; i < 8; i++) { loc[i] = s; s += deg[base + i]; }
    ts[t] = s;
    __syncthreads();
    for (int o = 1; o < 1024; o <<= 1) {
        int v = (t >= o) ? ts[t - o] : 0;
        __syncthreads();
        ts[t] += v;
        __syncthreads();
    }
    const int off = (t == 0) ? 0 : ts[t - 1];
#pragma unroll
    for (int i = 0; i < 8; i++) rs[base + i] = off + loc[i];
    if (t == 1023) rs[NN] = ts[1023];
}
__global__ void csrfill_kernel(const int* __restrict__ src, const int* __restrict__ dst,
                               int E, const int* __restrict__ rs,
                               int* __restrict__ cur, int* __restrict__ csr) {
    int e = blockIdx.x * 256 + threadIdx.x;
    if (e >= E) return;
    int d = dst[e];
    int slot = rs[d] + atomicAdd(&cur[d], 1);
    csr[slot] = src[e];
}
__global__ void gcn_self_kernel(const float* __restrict__ h,
                                const float* __restrict__ dinv,
                                float* __restrict__ c) {
    int idx = blockIdx.x * 256 + threadIdx.x;
    int v = idx >> 8;
    float dv = dinv[v];
    c[idx] = dv * dv * h[idx];
}
// c[d] += dinv[d] * sum_{s in N(d)} dinv[s]*h[s]   (one block per dst row)
__global__ void __launch_bounds__(256)
spmm_kernel(const int* __restrict__ rs, const int* __restrict__ csr,
            const float* __restrict__ dinv, const float* __restrict__ h,
            float* __restrict__ c) {
    const int d = blockIdx.x;
    const int t = threadIdx.x;
    const int b0 = rs[d], b1 = rs[d + 1];
    float acc = 0.f;
    for (int j = b0; j < b1; j++) {
        const int s = csr[j];
        acc += dinv[s] * h[(size_t)s * HDIM + t];
    }
    c[(size_t)d * HDIM + t] += dinv[d] * acc;
}

// ---------------------------------------------------------------------------
// Online softmax statistics over fp32 sim
// ---------------------------------------------------------------------------
__device__ __forceinline__ void sm_combine(float& m, float& s, float m2, float s2) {
    float M = fmaxf(m, m2);
    s = s * __expf(m - M) + s2 * __expf(m2 - M);
    m = M;
}
__global__ void rowstats_kernel(const float* __restrict__ sim,
                                float* __restrict__ rmax, float* __restrict__ rsum) {
    const int row = blockIdx.x;
    const float* p = sim + (size_t)row * NN;
    float m = -1e30f, s = 0.f;
    for (int c = threadIdx.x; c < NN; c += 256) {
        float x = p[c];
        if (x > m) { s = s * __expf(m - x) + 1.f; m = x; }
        else       { s += __expf(x - m); }
    }
#pragma unroll
    for (int o = 16; o > 0; o >>= 1) {
        float m2 = __shfl_xor_sync(0xffffffffu, m, o);
        float s2 = __shfl_xor_sync(0xffffffffu, s, o);
        sm_combine(m, s, m2, s2);
    }
    __shared__ float sm[8], ss[8];
    int w = threadIdx.x >> 5, l = threadIdx.x & 31;
    if (l == 0) { sm[w] = m; ss[w] = s; }
    __syncthreads();
    if (threadIdx.x == 0) {
        m = sm[0]; s = ss[0];
        for (int i = 1; i < 8; i++) sm_combine(m, s, sm[i], ss[i]);
        rmax[row] = m; rsum[row] = s;
    }
}
__global__ void colstats_band_kernel(const float* __restrict__ sim,
                                     float* __restrict__ band) {
    const int col = blockIdx.x * 32 + threadIdx.x;
    const int y = threadIdx.y;
    const int r0 = blockIdx.y * (NN / 8);
    float m = -1e30f, s = 0.f;
    for (int r = r0 + y; r < r0 + NN / 8; r += 8) {
        float x = sim[(size_t)r * NN + col];
        if (x > m) { s = s * __expf(m - x) + 1.f; m = x; }
        else       { s += __expf(x - m); }
    }
    __shared__ float sm[8][32], ss[8][32];
    sm[y][threadIdx.x] = m; ss[y][threadIdx.x] = s;
    __syncthreads();
    if (y == 0) {
        for (int i = 1; i < 8; i++) sm_combine(m, s, sm[i][threadIdx.x], ss[i][threadIdx.x]);
        band[((size_t)blockIdx.y * NN + col) * 2]     = m;
        band[((size_t)blockIdx.y * NN + col) * 2 + 1] = s;
    }
}
__global__ void colmerge_kernel(const float* __restrict__ band,
                                float* __restrict__ cmax, float* __restrict__ csum) {
    int col = blockIdx.x * 256 + threadIdx.x;
    float m = band[(size_t)col * 2], s = band[(size_t)col * 2 + 1];
#pragma unroll
    for (int b = 1; b < 8; b++)
        sm_combine(m, s, band[((size_t)b * NN + col) * 2],
                         band[((size_t)b * NN + col) * 2 + 1]);
    cmax[col] = m; csum[col] = s;
}

// ---------------------------------------------------------------------------
// cat = [c | f | f - att] -> bf16 hi/lo (att rows have stride din)
// ---------------------------------------------------------------------------
__global__ void cat_split_kernel(const float* __restrict__ c, const float* __restrict__ f,
                                 const float* __restrict__ att,
                                 __nv_bfloat16* __restrict__ cath,
                                 __nv_bfloat16* __restrict__ catl, int din) {
    const int catw = HDIM + 2 * din;
    size_t idx = (size_t)blockIdx.x * 256 + threadIdx.x;
    if (idx >= (size_t)NN * catw) return;
    int r = (int)(idx / catw), col = (int)(idx % catw);
    float v;
    if (col < HDIM)            v = c[(size_t)r * HDIM + col];
    else if (col < HDIM + din) v = f[(size_t)r * din + (col - HDIM)];
    else {
        int cc = col - HDIM - din;
        v = f[(size_t)r * din + cc] - att[(size_t)r * din + cc];
    }
    __nv_bfloat16 h = __float2bfloat16(v);
    cath[idx] = h;
    catl[idx] = __float2bfloat16(v - __bfloat162float(h));
}

// ---------------------------------------------------------------------------
// Gated readout + NTN tail
// ---------------------------------------------------------------------------
__global__ void zero_kernel(float* p, int n) {
    int i = blockIdx.x * 256 + threadIdx.x;
    if (i < n) p[i] = 0.f;
}
__global__ void preduce_kernel(const float* __restrict__ z,
                               const float* __restrict__ f,
                               float* __restrict__ p) {
    const int c = threadIdx.x;
    const int r0 = blockIdx.x * 64;
    float acc = 0.f;
    for (int r = r0; r < r0 + 64; r++)
        acc += z[(size_t)r * HDIM + c] * f[(size_t)r * HDIM + c];
    atomicAdd(&p[c], acc);
}
__global__ void ntn1_kernel(const float* __restrict__ p1,
                            const float* __restrict__ W,
                            float* __restrict__ tmp) {
    int g = blockIdx.x * 256 + threadIdx.x;
    float acc = 0.f;
    for (int i = 0; i < HDIM; i++) acc += p1[i] * W[(size_t)i * 8192 + g];
    tmp[g] = acc;
}
__global__ void tail_kernel(const float* __restrict__ p1, const float* __restrict__ p2,
                            const float* __restrict__ tmp,
                            const float* __restrict__ Wb, const float* __restrict__ tnb,
                            const float* __restrict__ fc1W, const float* __restrict__ fc1b,
                            const float* __restrict__ scW, const float* __restrict__ scb,
                            const float* __restrict__ avgv,
                            float* __restrict__ out, int out_size) {
    __shared__ float ntn[32];
    __shared__ float sv[16];
    const int t = threadIdx.x;
    float acc = tnb[t];
    for (int j = 0; j < HDIM; j++) acc += tmp[j * 32 + t] * p2[j];
    for (int k = 0; k < HDIM; k++)
        acc += Wb[t * 512 + k] * p1[k] + Wb[t * 512 + HDIM + k] * p2[k];
    ntn[t] = fmaxf(acc, 0.f);
    __syncthreads();
    if (t < 16) {
        float a = fc1b[t];
        for (int q = 0; q < 32; q++) a += ntn[q] * fc1W[q * 16 + t];
        sv[t] = tanhf(a);
    }
    __syncthreads();
    if (t == 0) {
        float a = scb[0];
        for (int q = 0; q < 16; q++) a += sv[q] * scW[q];
        float sc = 1.f / (1.f + expf(-a));
        out[0] = sc;
        if (out_size > 1) out[1] = -logf(sc) * avgv[0];
    }
}

// ---------------------------------------------------------------------------
// Host launcher
// ---------------------------------------------------------------------------
extern "C" void kernel_launch(void* const* d_in, const int* in_sizes, int n_in,
                              void* d_out, int out_size)
{
    const float* f1in  = (const float*)d_in[0];
    const float* f2in  = (const float*)d_in[1];
    const int*   ei1   = (const int*)d_in[2];
    const int*   ei2   = (const int*)d_in[3];
    const float* avgv  = (const float*)d_in[4];
    const float* gcnW[3] = {(const float*)d_in[5], (const float*)d_in[8],  (const float*)d_in[11]};
    const float* updW[3] = {(const float*)d_in[6], (const float*)d_in[9],  (const float*)d_in[12]};
    const float* updb[3] = {(const float*)d_in[7], (const float*)d_in[10], (const float*)d_in[13]};
    const float* gatedW = (const float*)d_in[14];
    const float* gatedb = (const float*)d_in[15];
    const float* tnW  = (const float*)d_in[16];
    const float* tnWb = (const float*)d_in[17];
    const float* tnb  = (const float*)d_in[18];
    const float* fc1W = (const float*)d_in[19];
    const float* fc1b = (const float*)d_in[20];
    const float* scW  = (const float*)d_in[21];
    const float* scb  = (const float*)d_in[22];

    const int E = in_sizes[2] / 2;

    float *sim, *h1, *h2, *c1, *c2, *att1, *att2, *fa1, *fa2, *fb1, *fb2;
    float *rmax, *rsum, *cmax, *csum, *bandp, *dinv1, *dinv2, *pvec, *tmp;
    __nv_bfloat16 *Pr, *Pc, *fh1, *fl1, *fh2, *fl2, *f1T, *f2T;
    __nv_bfloat16 *cath1, *catl1, *cath2, *catl2;
    __nv_bfloat16 *gcnWTh, *gcnWTl, *updWTh, *updWTl, *gatedWTh, *gatedWTl;
    int *rs1, *rs2, *csr1, *csr2, *degi, *cur;
    cudaGetSymbolAddress((void**)&sim,  g_sim);
    cudaGetSymbolAddress((void**)&Pr,   g_Pr);
    cudaGetSymbolAddress((void**)&Pc,   g_Pc);
    cudaGetSymbolAddress((void**)&fh1,  g_fh1);
    cudaGetSymbolAddress((void**)&fl1,  g_fl1);
    cudaGetSymbolAddress((void**)&fh2,  g_fh2);
    cudaGetSymbolAddress((void**)&fl2,  g_fl2);
    cudaGetSymbolAddress((void**)&f1T,  g_f1T);
    cudaGetSymbolAddress((void**)&f2T,  g_f2T);
    cudaGetSymbolAddress((void**)&h1,   g_h1);
    cudaGetSymbolAddress((void**)&h2,   g_h2);
    cudaGetSymbolAddress((void**)&c1,   g_c1);
    cudaGetSymbolAddress((void**)&c2,   g_c2);
    cudaGetSymbolAddress((void**)&att1, g_att1);
    cudaGetSymbolAddress((void**)&att2, g_att2);
    cudaGetSymbolAddress((void**)&fa1,  g_fa1);
    cudaGetSymbolAddress((void**)&fa2,  g_fa2);
    cudaGetSymbolAddress((void**)&fb1,  g_fb1);
    cudaGetSymbolAddress((void**)&fb2,  g_fb2);
    cudaGetSymbolAddress((void**)&cath1, g_cath1);
    cudaGetSymbolAddress((void**)&catl1, g_catl1);
    cudaGetSymbolAddress((void**)&cath2, g_cath2);
    cudaGetSymbolAddress((void**)&catl2, g_catl2);
    cudaGetSymbolAddress((void**)&rmax, g_rmax);
    cudaGetSymbolAddress((void**)&rsum, g_rsum);
    cudaGetSymbolAddress((void**)&cmax, g_cmax);
    cudaGetSymbolAddress((void**)&csum, g_csum);
    cudaGetSymbolAddress((void**)&bandp, g_band);
    cudaGetSymbolAddress((void**)&dinv1, g_dinv1);
    cudaGetSymbolAddress((void**)&dinv2, g_dinv2);
    cudaGetSymbolAddress((void**)&pvec, g_p);
    cudaGetSymbolAddress((void**)&tmp,  g_tmp);
    cudaGetSymbolAddress((void**)&rs1,  g_rs1);
    cudaGetSymbolAddress((void**)&rs2,  g_rs2);
    cudaGetSymbolAddress((void**)&csr1, g_csr1);
    cudaGetSymbolAddress((void**)&csr2, g_csr2);
    cudaGetSymbolAddress((void**)&degi, g_degi);
    cudaGetSymbolAddress((void**)&cur,  g_cur);
    cudaGetSymbolAddress((void**)&gcnWTh, g_gcnWT_h);
    cudaGetSymbolAddress((void**)&gcnWTl, g_gcnWT_l);
    cudaGetSymbolAddress((void**)&updWTh, g_updWT_h);
    cudaGetSymbolAddress((void**)&updWTl, g_updWT_l);
    cudaGetSymbolAddress((void**)&gatedWTh, g_gatedWT_h);
    cudaGetSymbolAddress((void**)&gatedWTl, g_gatedWT_l);

    const int SMEM_SPLIT = 2 * (2 * A_TB + 2 * B_TB);  // 98304
    const int SMEM_PLAIN = 2 * (A_TB + B_TB);          // 49152
    cudaFuncSetAttribute(mma_gemm<1, 0, 0>, cudaFuncAttributeMaxDynamicSharedMemorySize, SMEM_SPLIT);
    cudaFuncSetAttribute(mma_gemm<0, 1, 1>, cudaFuncAttributeMaxDynamicSharedMemorySize, SMEM_PLAIN);

    // --- one-time weight transpose + hi/lo split ---
    const dim3 wtb(32, 8);
    for (int L = 0; L < 3; L++) {
        const int dk = (L == 0) ? DIN0 : HDIM;
        const int cw = HDIM + 2 * dk;
        wtsplit_kernel<<<dim3(dk / 32, HDIM / 32), wtb>>>(
            gcnW[L], gcnWTh + L * HDIM * HDIM, gcnWTl + L * HDIM * HDIM, dk, HDIM);
        wtsplit_kernel<<<dim3(cw / 32, HDIM / 32), wtb>>>(
            updW[L], updWTh + L * HDIM * 768, updWTl + L * HDIM * 768, cw, HDIM);
    }
    wtsplit_kernel<<<dim3(HDIM / 32, HDIM / 32), wtb>>>(gatedW, gatedWTh, gatedWTl, HDIM, HDIM);

    // --- degree normalization ---
    fill1_kernel<<<(NN + 255) / 256, 256>>>(dinv1, NN);
    fill1_kernel<<<(NN + 255) / 256, 256>>>(dinv2, NN);
    degcnt_kernel<<<(E + 255) / 256, 256>>>(ei1 + E, E, dinv1);
    degcnt_kernel<<<(E + 255) / 256, 256>>>(ei2 + E, E, dinv2);
    rsqrt_kernel<<<(NN + 255) / 256, 256>>>(dinv1, NN);
    rsqrt_kernel<<<(NN + 255) / 256, 256>>>(dinv2, NN);

    // --- one-time CSR build (edges identical across layers) ---
    zeroint_kernel<<<NN / 256, 256>>>(degi, NN);
    degint_kernel<<<(E + 255) / 256, 256>>>(ei1 + E, E, degi);
    scan_kernel<<<1, 1024>>>(degi, rs1);
    zeroint_kernel<<<NN / 256, 256>>>(cur, NN);
    csrfill_kernel<<<(E + 255) / 256, 256>>>(ei1, ei1 + E, E, rs1, cur, csr1);
    zeroint_kernel<<<NN / 256, 256>>>(degi, NN);
    degint_kernel<<<(E + 255) / 256, 256>>>(ei2 + E, E, degi);
    scan_kernel<<<1, 1024>>>(degi, rs2);
    zeroint_kernel<<<NN / 256, 256>>>(cur, NN);
    csrfill_kernel<<<(E + 255) / 256, 256>>>(ei2, ei2 + E, E, rs2, cur, csr2);

    const float* f1p = f1in;
    const float* f2p = f2in;
    int din = DIN0;

    for (int L = 0; L < 3; L++) {
        float* o1 = (L == 1) ? fa1 : fb1;
        float* o2 = (L == 1) ? fa2 : fb2;
        const __nv_bfloat16* gWh = gcnWTh + L * HDIM * HDIM;
        const __nv_bfloat16* gWl = gcnWTl + L * HDIM * HDIM;
        const __nv_bfloat16* uWh = updWTh + L * HDIM * 768;
        const __nv_bfloat16* uWl = updWTl + L * HDIM * 768;

        // zero att accumulators (split-K atomic epilogue)
        zero_kernel<<<NN * din / 256, 256>>>(att1, NN * din);
        zero_kernel<<<NN * din / 256, 256>>>(att2, NN * din);

        // bf16 forms of features
        split_bf16_kernel<<<NN * din / 256, 256>>>(f1p, fh1, fl1, NN * din);
        split_bf16_kernel<<<NN * din / 256, 256>>>(f2p, fh2, fl2, NN * din);
        transpose_bf16_kernel<<<dim3(din / 32, NN / 32), dim3(32, 8)>>>(f1p, f1T, din);
        transpose_bf16_kernel<<<dim3(din / 32, NN / 32), dim3(32, 8)>>>(f2p, f2T, din);

        // GCN: h = f @ Wg (split bf16 tensor), then CSR aggregation
        mma_gemm<1, 0, 0><<<dim3(HDIM / 64, NN / 128), 256, SMEM_SPLIT>>>(
            fh1, fl1, gWh, gWl, h1, HDIM, din, nullptr, nullptr, 0);
        mma_gemm<1, 0, 0><<<dim3(HDIM / 64, NN / 128), 256, SMEM_SPLIT>>>(
            fh2, fl2, gWh, gWl, h2, HDIM, din, nullptr, nullptr, 0);
        gcn_self_kernel<<<NN * HDIM / 256, 256>>>(h1, dinv1, c1);
        gcn_self_kernel<<<NN * HDIM / 256, 256>>>(h2, dinv2, c2);
        spmm_kernel<<<NN, 256>>>(rs1, csr1, dinv1, h1, c1);
        spmm_kernel<<<NN, 256>>>(rs2, csr2, dinv2, h2, c2);

        // sim = f1 @ f2^T (split bf16 => fp32-grade)
        mma_gemm<1, 0, 0><<<dim3(NN / 64, NN / 128), 256, SMEM_SPLIT>>>(
            fh1, fl1, fh2, fl2, sim, NN, din, nullptr, nullptr, 0);

        // softmax statistics (fp32): row stats + banded col stats
        rowstats_kernel<<<NN, 256>>>(sim, rmax, rsum);
        colstats_band_kernel<<<dim3(NN / 32, 8), dim3(32, 8)>>>(sim, bandp);
        colmerge_kernel<<<NN / 256, 256>>>(bandp, cmax, csum);

        // P matrices (bf16)
        exp_convert_kernel<<<dim3(NN / 32, NN / 32), dim3(32, 8)>>>(sim, rmax, cmax, Pr, Pc);

        // att1 / att2 with split-K (512 blocks each)
        const int zk = (din == DIN0) ? 4 : 2;
        mma_gemm<0, 1, 1><<<dim3(din / 64, NN / 128, zk), 256, SMEM_PLAIN>>>(
            Pr, nullptr, f2T, nullptr, att1, din, NN, rsum, nullptr, 0);
        mma_gemm<0, 1, 1><<<dim3(din / 64, NN / 128, zk), 256, SMEM_PLAIN>>>(
            Pc, nullptr, f1T, nullptr, att2, din, NN, csum, nullptr, 0);

        // cat (bf16 hi/lo) + update GEMM (+tanh except last layer)
        const int catw = HDIM + 2 * din;
        const int nel = NN * catw;
        cat_split_kernel<<<(nel + 255) / 256, 256>>>(c1, f1p, att1, cath1, catl1, din);
        cat_split_kernel<<<(nel + 255) / 256, 256>>>(c2, f2p, att2, cath2, catl2, din);
        const int act = (L == 2) ? 0 : 1;
        mma_gemm<1, 0, 0><<<dim3(HDIM / 64, NN / 128), 256, SMEM_SPLIT>>>(
            cath1, catl1, uWh, uWl, o1, HDIM, catw, nullptr, updb[L], act);
        mma_gemm<1, 0, 0><<<dim3(HDIM / 64, NN / 128), 256, SMEM_SPLIT>>>(
            cath2, catl2, uWh, uWl, o2, HDIM, catw, nullptr, updb[L], act);

        f1p = o1; f2p = o2; din = HDIM;
    }

    // --- gated readout (split bf16 tensor + sigmoid epilogue) ---
    split_bf16_kernel<<<NN * HDIM / 256, 256>>>(f1p, fh1, fl1, NN * HDIM);
    split_bf16_kernel<<<NN * HDIM / 256, 256>>>(f2p, fh2, fl2, NN * HDIM);
    mma_gemm<1, 0, 0><<<dim3(HDIM / 64, NN / 128), 256, SMEM_SPLIT>>>(
        fh1, fl1, gatedWTh, gatedWTl, h1, HDIM, HDIM, nullptr, gatedb, 2);
    mma_gemm<1, 0, 0><<<dim3(HDIM / 64, NN / 128), 256, SMEM_SPLIT>>>(
        fh2, fl2, gatedWTh, gatedWTl, h2, HDIM, HDIM, nullptr, gatedb, 2);
    zero_kernel<<<2, 256>>>(pvec, 2 * HDIM);
    preduce_kernel<<<NN / 64, 256>>>(h1, f1p, pvec);
    preduce_kernel<<<NN / 64, 256>>>(h2, f2p, pvec + HDIM);

    // --- NTN + head ---
    ntn1_kernel<<<32, 256>>>(pvec, tnW, tmp);
    tail_kernel<<<1, 32>>>(pvec, pvec + HDIM, tmp, tnWb, tnb,
                           fc1W, fc1b, scW, scb, avgv, (float*)d_out, out_size);
}